// round 4
// baseline (speedup 1.0000x reference)
#include <cuda_runtime.h>
#include <math.h>

// Problem constants
#define Nn 2
#define Tt 2048
#define DMc 1024
#define Hh 8
#define Ee 4
#define Ll 32
#define DKc 64
#define DVc 64
#define NT (Nn*Tt)           // 4096 tokens
#define REC_T (Tt+Ll)        // 2080 rec positions per (n,e)
#define M_CH (Tt/Ll)         // 64 chunks

// Scratch (allocation-free rule: __device__ globals)
__device__ float d_K[NT*Hh*DKc];       // (token, h*64+d)
__device__ float d_V[NT*Hh*DVc];
__device__ float d_Q[NT*Hh*DKc];
__device__ float d_Graw[NT*Hh*Ee];     // (token, h*4+e) pre-sigmoid
__device__ float d_A[Nn*Ee*Tt];        // (n,e,t)
__device__ float d_gK[Nn*Ee*Tt*DKc];   // (n,e,t,d)
__device__ float d_gV[Nn*Ee*Tt*DVc];
__device__ float d_recK[Nn*Ee*REC_T*DKc]; // (n,e,pos,d), pos 0..L-1 = init
__device__ float d_recV[Nn*Ee*REC_T*DVc];
__device__ float d_Y[NT*Hh*DVc];       // (token, h*64+d)

// ---------------------------------------------------------------------------
// Generic fp32 tiled GEMM.
//  BT=true : C[M,Ncol] = A[M,K] * B^T,  B stored (Ncol,K) row-major
//  BT=false: C[M,Ncol] = A[M,K] * B,    B stored (K,Ncol) row-major
// Tile 64x64x16, 256 threads, 4x4 register micro-tile.
// Assumes M % 64 == 0 and K % 16 == 0 (true for all uses here); guards Ncol.
// ---------------------------------------------------------------------------
template<bool BT>
__global__ void __launch_bounds__(256) gemm_kernel(const float* __restrict__ A,
                                                   const float* __restrict__ B,
                                                   float* __restrict__ C,
                                                   int M, int Ncol, int K) {
    __shared__ float As[16][64];
    __shared__ float Bs[16][68];
    const int tid = threadIdx.x;
    const int tx = tid & 15, ty = tid >> 4;
    const int bm = blockIdx.y * 64, bn = blockIdx.x * 64;
    float acc[4][4] = {};
    for (int k0 = 0; k0 < K; k0 += 16) {
        #pragma unroll
        for (int i = 0; i < 4; i++) {
            int idx = tid + i * 256;
            int m = idx >> 4, kk = idx & 15;
            As[kk][m] = A[(bm + m) * K + k0 + kk];
        }
        if (BT) {
            #pragma unroll
            for (int i = 0; i < 4; i++) {
                int idx = tid + i * 256;
                int nn = idx >> 4, kk = idx & 15;
                int gn = bn + nn;
                Bs[kk][nn] = (gn < Ncol) ? B[gn * K + k0 + kk] : 0.f;
            }
        } else {
            #pragma unroll
            for (int i = 0; i < 4; i++) {
                int idx = tid + i * 256;
                int kk = idx >> 6, nn = idx & 63;
                int gn = bn + nn;
                Bs[kk][nn] = (gn < Ncol) ? B[(k0 + kk) * Ncol + gn] : 0.f;
            }
        }
        __syncthreads();
        #pragma unroll
        for (int kk = 0; kk < 16; kk++) {
            float a[4], b[4];
            #pragma unroll
            for (int i = 0; i < 4; i++) a[i] = As[kk][ty * 4 + i];
            #pragma unroll
            for (int j = 0; j < 4; j++) b[j] = Bs[kk][tx * 4 + j];
            #pragma unroll
            for (int i = 0; i < 4; i++)
                #pragma unroll
                for (int j = 0; j < 4; j++)
                    acc[i][j] += a[i] * b[j];
        }
        __syncthreads();
    }
    #pragma unroll
    for (int i = 0; i < 4; i++) {
        int gm = bm + ty * 4 + i;
        #pragma unroll
        for (int j = 0; j < 4; j++) {
            int gn = bn + tx * 4 + j;
            if (gn < Ncol) C[gm * Ncol + gn] = acc[i][j];
        }
    }
}

// ---------------------------------------------------------------------------
// Gating: per (n,e,t) compute gated_K, gated_V (sum over heads), and A.
// One block (128 threads) per (n,e,t).
// ---------------------------------------------------------------------------
__global__ void __launch_bounds__(128) gated_kernel(const float* __restrict__ bG) {
    const int blk = blockIdx.x;
    const int t = blk % Tt;
    const int e = (blk / Tt) % Ee;
    const int n = blk / (Tt * Ee);
    const int token = n * Tt + t;
    __shared__ float g[Hh];
    const int tid = threadIdx.x;
    if (tid < Hh) {
        float x = d_Graw[token * (Hh * Ee) + tid * Ee + e] + bG[tid * Ee + e];
        g[tid] = 1.f / (1.f + expf(-x));
    }
    __syncthreads();
    if (tid < 64) {
        float s = 0.f;
        #pragma unroll
        for (int h = 0; h < Hh; h++) s += g[h] * d_K[token * (Hh * DKc) + h * DKc + tid];
        d_gK[((n * Ee + e) * Tt + t) * DKc + tid] = s;
    } else {
        int dd = tid - 64;
        float s = 0.f;
        #pragma unroll
        for (int h = 0; h < Hh; h++) s += g[h] * d_V[token * (Hh * DVc) + h * DVc + dd];
        d_gV[((n * Ee + e) * Tt + t) * DVc + dd] = s;
    }
    if (tid == 0) {
        float sa = 0.f;
        #pragma unroll
        for (int h = 0; h < Hh; h++) sa += g[h];
        d_A[(n * Ee + e) * Tt + t] = 1.f - sa;
    }
}

// ---------------------------------------------------------------------------
// Scan: L-strided recurrence rec[t] = A[t]*rec[t-L] + gated[t].
// The reference's associative_scan over chunk axis m == for each lane l:
//   y_m = A[m*L+l]*y_{m-1} + g[m*L+l], y_{-1} = init[l].
// rec buffer = concat(init (L rows), next (T rows)).
// One block per (n,e,l): 128 threads (d<64 -> K stream, else V stream).
// ---------------------------------------------------------------------------
__global__ void __launch_bounds__(128) scan_kernel(const float* __restrict__ initK,
                                                   const float* __restrict__ initV) {
    const int b = blockIdx.x;             // Nn*Ee*Ll = 256 blocks
    const int l = b % Ll;
    const int e = (b / Ll) % Ee;
    const int n = b / (Ll * Ee);
    const int d = threadIdx.x;
    const bool isK = d < 64;
    const int dd = isK ? d : d - 64;
    const float* init = isK ? initK : initV;
    const float* gsrc = isK ? d_gK : d_gV;
    float* rec = isK ? d_recK : d_recV;
    const int ne = n * Ee + e;
    float y = init[(e * Ll + l) * 64 + dd];
    rec[(ne * REC_T + l) * 64 + dd] = y;
    const float* Arow = d_A + ne * Tt;
    const float* grow = gsrc + ne * Tt * 64;
    float* rrow = rec + (ne * REC_T + Ll) * 64;
    #pragma unroll 4
    for (int m = 0; m < M_CH; m++) {
        int t = m * Ll + l;
        y = Arow[t] * y + grow[t * 64 + dd];
        rrow[t * 64 + dd] = y;
    }
}

// ---------------------------------------------------------------------------
// Attention: one block per token (n,t); all H=8 heads share the same
// 128-slot key/value window (E=4 experts x L=32 positions).
// Window slot j: e=j>>5, pos=t+(j&31)+1 in the rec timeline.
// ---------------------------------------------------------------------------
__global__ void __launch_bounds__(256) attn_kernel() {
    extern __shared__ float smem[];
    float* qs = smem;                      // 512
    float* Ks = qs + Hh * DKc;             // 128*65 (padded rows)
    float* Vs = Ks + 128 * 65;             // 128*65
    float* sc = Vs + 128 * 65;             // 8*128
    const int token = blockIdx.x;
    const int n = token / Tt, t = token % Tt;
    const int tid = threadIdx.x;

    qs[tid]       = d_Q[token * 512 + tid];
    qs[tid + 256] = d_Q[token * 512 + tid + 256];

    for (int i = tid; i < 128 * 64; i += 256) {
        int j = i >> 6, dd = i & 63;
        int e = j >> 5;
        int pos = t + (j & 31) + 1;                 // <= 2079 < REC_T
        int off = ((n * Ee + e) * REC_T + pos) * 64 + dd;
        Ks[j * 65 + dd] = d_recK[off];
        Vs[j * 65 + dd] = d_recV[off];
    }
    __syncthreads();

    // scores: 8 heads x 128 slots = 1024 tasks
    #pragma unroll
    for (int r = 0; r < 4; r++) {
        int task = tid + r * 256;
        int h = task >> 7, j = task & 127;
        const float* qrow = qs + h * 64;
        const float* krow = Ks + j * 65;
        float s = 0.f;
        #pragma unroll
        for (int d = 0; d < 64; d++) s += qrow[d] * krow[d];
        sc[h * 128 + j] = s * 0.125f;               // 1/sqrt(64)
    }
    __syncthreads();

    // softmax over 128 slots: warp w handles head h=w
    {
        int h = tid >> 5, lane = tid & 31;
        float v0 = sc[h * 128 + lane];
        float v1 = sc[h * 128 + lane + 32];
        float v2 = sc[h * 128 + lane + 64];
        float v3 = sc[h * 128 + lane + 96];
        float mx = fmaxf(fmaxf(v0, v1), fmaxf(v2, v3));
        #pragma unroll
        for (int o = 16; o; o >>= 1) mx = fmaxf(mx, __shfl_xor_sync(0xffffffffu, mx, o));
        float e0 = expf(v0 - mx), e1 = expf(v1 - mx);
        float e2 = expf(v2 - mx), e3 = expf(v3 - mx);
        float ssum = e0 + e1 + e2 + e3;
        #pragma unroll
        for (int o = 16; o; o >>= 1) ssum += __shfl_xor_sync(0xffffffffu, ssum, o);
        float inv = 1.f / ssum;
        sc[h * 128 + lane]      = e0 * inv;
        sc[h * 128 + lane + 32] = e1 * inv;
        sc[h * 128 + lane + 64] = e2 * inv;
        sc[h * 128 + lane + 96] = e3 * inv;
    }
    __syncthreads();

    // output: 8 heads x 64 dims = 512 outputs
    #pragma unroll
    for (int r = 0; r < 2; r++) {
        int o = tid + r * 256;
        int h = o >> 6, dd = o & 63;
        const float* arow = sc + h * 128;
        float acc = 0.f;
        #pragma unroll 4
        for (int j = 0; j < 128; j++) acc += arow[j] * Vs[j * 65 + dd];
        d_Y[token * 512 + o] = acc;
    }
}

// ---------------------------------------------------------------------------
extern "C" void kernel_launch(void* const* d_in, const int* in_sizes, int n_in,
                              void* d_out, int out_size) {
    const float* X  = (const float*)d_in[0];
    const float* wG = (const float*)d_in[1];
    const float* bG = (const float*)d_in[2];
    const float* wK = (const float*)d_in[3];
    const float* wV = (const float*)d_in[4];
    const float* wQ = (const float*)d_in[5];
    const float* wO = (const float*)d_in[6];
    const float* iK = (const float*)d_in[7];
    const float* iV = (const float*)d_in[8];
    float* out = (float*)d_out;

    float *pK, *pV, *pQ, *pG, *pY;
    cudaGetSymbolAddress((void**)&pK, d_K);
    cudaGetSymbolAddress((void**)&pV, d_V);
    cudaGetSymbolAddress((void**)&pQ, d_Q);
    cudaGetSymbolAddress((void**)&pG, d_Graw);
    cudaGetSymbolAddress((void**)&pY, d_Y);

    // Projections: C = X * W^T  (W flattened row-major (out_features, DM))
    gemm_kernel<true><<<dim3(8, 64), 256>>>(X, wK, pK, NT, Hh * DKc, DMc);
    gemm_kernel<true><<<dim3(8, 64), 256>>>(X, wV, pV, NT, Hh * DVc, DMc);
    gemm_kernel<true><<<dim3(8, 64), 256>>>(X, wQ, pQ, NT, Hh * DKc, DMc);
    gemm_kernel<true><<<dim3(1, 64), 256>>>(X, wG, pG, NT, Hh * Ee, DMc);

    gated_kernel<<<Nn * Ee * Tt, 128>>>(bG);
    scan_kernel<<<Nn * Ee * Ll, 128>>>(iK, iV);

    static const size_t attn_smem = (512 + 2 * 128 * 65 + 8 * 128) * sizeof(float);
    cudaFuncSetAttribute(attn_kernel, cudaFuncAttributeMaxDynamicSharedMemorySize,
                         (int)attn_smem);
    attn_kernel<<<NT, 256, attn_smem>>>();

    // Output: out = Y * w_O  (w_O stored (512, 1024) row-major, not transposed)
    gemm_kernel<false><<<dim3(16, 64), 256>>>(pY, wO, out, NT, DMc, Hh * DVc);
}

// round 5
// speedup vs baseline: 2.7567x; 2.7567x over previous
#include <cuda_runtime.h>
#include <math.h>

// Problem constants
#define Nn 2
#define Tt 2048
#define DMc 1024
#define Hh 8
#define Ee 4
#define Ll 32
#define DKc 64
#define DVc 64
#define NT (Nn*Tt)           // 4096 tokens
#define REC_T (Tt+Ll)        // 2080 rec positions per (n,e)
#define M_CH (Tt/Ll)         // 64 chunks

// Scratch (allocation-free rule: __device__ globals)
__device__ float d_K[NT*Hh*DKc];       // (token, h*64+d)
__device__ float d_V[NT*Hh*DVc];
__device__ float d_Q[NT*Hh*DKc];
__device__ float d_Gsig[NT*Hh*Ee];     // (token, h*4+e) POST-sigmoid
__device__ float d_A[Nn*Ee*Tt];        // (n,e,t)
__device__ float d_gK[Nn*Ee*Tt*DKc];   // (n,e,t,d)
__device__ float d_gV[Nn*Ee*Tt*DVc];
__device__ float d_recK[Nn*Ee*REC_T*DKc]; // (n,e,pos,d), pos 0..L-1 = init
__device__ float d_recV[Nn*Ee*REC_T*DVc];
__device__ float d_Y[NT*Hh*DVc];       // (token, h*64+d)

// ---------------------------------------------------------------------------
// fp32 GEMM, 128x128x16 tile, 256 threads, 8x8 micro-tile, double-buffered.
//  BT=true : C[M,Ncol] = A[M,K] * B^T,  B stored (Ncol,K) row-major
//  BT=false: C[M,Ncol] = A[M,K] * B,    B stored (K,Ncol) row-major
// Requires M%128==0, Ncol%128==0, K%16==0 (true for all uses here).
// ---------------------------------------------------------------------------
template<bool BT>
__global__ void __launch_bounds__(256) gemm128(const float* __restrict__ A,
                                               const float* __restrict__ B,
                                               float* __restrict__ C,
                                               int M, int Ncol, int K) {
    __shared__ float As[2][16][132];
    __shared__ float Bs[2][16][132];
    const int tid = threadIdx.x;
    const int tx = tid & 15, ty = tid >> 4;
    const int bm = blockIdx.y * 128, bn = blockIdx.x * 128;
    const int aoff = ty * 8, boff = tx * 8;

    // loader indexing (A and BT-B: row r of 128, float4 q of 4 along K)
    const int r0 = tid >> 2,        q0 = tid & 3;           // idx = tid
    const int r1 = (tid + 256) >> 2, q1 = tid & 3;          // idx = tid+256
    // !BT B loader: 16 k-rows x 32 float4 cols
    const int kkb0 = tid >> 5,       nb0 = tid & 31;
    const int kkb1 = (tid + 256) >> 5, nb1 = tid & 31;

    float4 ra0, ra1, rb0, rb1;

    auto fetch = [&](int k0) {
        ra0 = *(const float4*)(A + (size_t)(bm + r0) * K + k0 + q0 * 4);
        ra1 = *(const float4*)(A + (size_t)(bm + r1) * K + k0 + q1 * 4);
        if (BT) {
            rb0 = *(const float4*)(B + (size_t)(bn + r0) * K + k0 + q0 * 4);
            rb1 = *(const float4*)(B + (size_t)(bn + r1) * K + k0 + q1 * 4);
        } else {
            rb0 = *(const float4*)(B + (size_t)(k0 + kkb0) * Ncol + bn + nb0 * 4);
            rb1 = *(const float4*)(B + (size_t)(k0 + kkb1) * Ncol + bn + nb1 * 4);
        }
    };
    auto store = [&](int b) {
        As[b][q0 * 4 + 0][r0] = ra0.x; As[b][q0 * 4 + 1][r0] = ra0.y;
        As[b][q0 * 4 + 2][r0] = ra0.z; As[b][q0 * 4 + 3][r0] = ra0.w;
        As[b][q1 * 4 + 0][r1] = ra1.x; As[b][q1 * 4 + 1][r1] = ra1.y;
        As[b][q1 * 4 + 2][r1] = ra1.z; As[b][q1 * 4 + 3][r1] = ra1.w;
        if (BT) {
            Bs[b][q0 * 4 + 0][r0] = rb0.x; Bs[b][q0 * 4 + 1][r0] = rb0.y;
            Bs[b][q0 * 4 + 2][r0] = rb0.z; Bs[b][q0 * 4 + 3][r0] = rb0.w;
            Bs[b][q1 * 4 + 0][r1] = rb1.x; Bs[b][q1 * 4 + 1][r1] = rb1.y;
            Bs[b][q1 * 4 + 2][r1] = rb1.z; Bs[b][q1 * 4 + 3][r1] = rb1.w;
        } else {
            *(float4*)&Bs[b][kkb0][nb0 * 4] = rb0;
            *(float4*)&Bs[b][kkb1][nb1 * 4] = rb1;
        }
    };

    float acc[8][8] = {};
    auto compute = [&](int b) {
        #pragma unroll
        for (int kk = 0; kk < 16; kk++) {
            float4 a0 = *(const float4*)&As[b][kk][aoff];
            float4 a1 = *(const float4*)&As[b][kk][aoff + 4];
            float4 b0 = *(const float4*)&Bs[b][kk][boff];
            float4 b1 = *(const float4*)&Bs[b][kk][boff + 4];
            float av[8] = {a0.x, a0.y, a0.z, a0.w, a1.x, a1.y, a1.z, a1.w};
            float bv[8] = {b0.x, b0.y, b0.z, b0.w, b1.x, b1.y, b1.z, b1.w};
            #pragma unroll
            for (int i = 0; i < 8; i++)
                #pragma unroll
                for (int j = 0; j < 8; j++)
                    acc[i][j] += av[i] * bv[j];
        }
    };

    fetch(0);
    store(0);
    __syncthreads();
    int buf = 0;
    const int nk = K / 16;
    for (int kt = 1; kt < nk; kt++) {
        fetch(kt * 16);
        compute(buf);
        store(buf ^ 1);
        __syncthreads();
        buf ^= 1;
    }
    compute(buf);

    #pragma unroll
    for (int i = 0; i < 8; i++) {
        float* crow = C + (size_t)(bm + aoff + i) * Ncol + bn + boff;
        float4 c0 = {acc[i][0], acc[i][1], acc[i][2], acc[i][3]};
        float4 c1 = {acc[i][4], acc[i][5], acc[i][6], acc[i][7]};
        *(float4*)crow = c0;
        *(float4*)(crow + 4) = c1;
    }
}

// ---------------------------------------------------------------------------
// G projection + bias + sigmoid.
// Block = 8 tokens, 256 threads (8 warps). Warp w computes output rows
// o = 4w..4w+3 for all 8 tokens. X rows staged in smem.
// ---------------------------------------------------------------------------
__global__ void __launch_bounds__(256) g_kernel(const float* __restrict__ X,
                                                const float* __restrict__ wG,
                                                const float* __restrict__ bG) {
    __shared__ float xs[8][1024];
    const int tid = threadIdx.x;
    const int token0 = blockIdx.x * 8;
    // stage 8 X rows: 2048 float4, 8 per thread, coalesced
    #pragma unroll
    for (int i = 0; i < 8; i++) {
        int idx = tid + i * 256;              // float4 index 0..2047
        int tok = idx >> 8, c4 = idx & 255;
        *(float4*)&xs[tok][c4 * 4] =
            *(const float4*)(X + (size_t)(token0 + tok) * DMc + c4 * 4);
    }
    __syncthreads();

    const int w = tid >> 5, lane = tid & 31;
    float acc[4][8] = {};
    #pragma unroll 4
    for (int j = 0; j < 32; j++) {
        int k = j * 32 + lane;
        float wv[4];
        #pragma unroll
        for (int o = 0; o < 4; o++)
            wv[o] = wG[(size_t)(w * 4 + o) * DMc + k];
        #pragma unroll
        for (int tok = 0; tok < 8; tok++) {
            float xv = xs[tok][k];
            #pragma unroll
            for (int o = 0; o < 4; o++)
                acc[o][tok] += wv[o] * xv;
        }
    }
    #pragma unroll
    for (int o = 0; o < 4; o++) {
        float bias = bG[w * 4 + o];
        #pragma unroll
        for (int tok = 0; tok < 8; tok++) {
            float v = acc[o][tok];
            #pragma unroll
            for (int off = 16; off; off >>= 1)
                v += __shfl_xor_sync(0xffffffffu, v, off);
            if (lane == 0)
                d_Gsig[(size_t)(token0 + tok) * (Hh * Ee) + w * 4 + o] =
                    1.f / (1.f + expf(-(v + bias)));
        }
    }
}

// ---------------------------------------------------------------------------
// Gating: per (n,e,t) compute gated_K, gated_V (sum over heads), and A.
// ---------------------------------------------------------------------------
__global__ void __launch_bounds__(128) gated_kernel() {
    const int blk = blockIdx.x;
    const int t = blk % Tt;
    const int e = (blk / Tt) % Ee;
    const int n = blk / (Tt * Ee);
    const int token = n * Tt + t;
    __shared__ float g[Hh];
    const int tid = threadIdx.x;
    if (tid < Hh)
        g[tid] = d_Gsig[token * (Hh * Ee) + tid * Ee + e];
    __syncthreads();
    if (tid < 64) {
        float s = 0.f;
        #pragma unroll
        for (int h = 0; h < Hh; h++) s += g[h] * d_K[token * (Hh * DKc) + h * DKc + tid];
        d_gK[((n * Ee + e) * Tt + t) * DKc + tid] = s;
    } else {
        int dd = tid - 64;
        float s = 0.f;
        #pragma unroll
        for (int h = 0; h < Hh; h++) s += g[h] * d_V[token * (Hh * DVc) + h * DVc + dd];
        d_gV[((n * Ee + e) * Tt + t) * DVc + dd] = s;
    }
    if (tid == 0) {
        float sa = 0.f;
        #pragma unroll
        for (int h = 0; h < Hh; h++) sa += g[h];
        d_A[(n * Ee + e) * Tt + t] = 1.f - sa;
    }
}

// ---------------------------------------------------------------------------
// Scan: L-strided recurrence rec[t] = A[t]*rec[t-L] + gated[t].
// ---------------------------------------------------------------------------
__global__ void __launch_bounds__(128) scan_kernel(const float* __restrict__ initK,
                                                   const float* __restrict__ initV) {
    const int b = blockIdx.x;             // Nn*Ee*Ll = 256 blocks
    const int l = b % Ll;
    const int e = (b / Ll) % Ee;
    const int n = b / (Ll * Ee);
    const int d = threadIdx.x;
    const bool isK = d < 64;
    const int dd = isK ? d : d - 64;
    const float* init = isK ? initK : initV;
    const float* gsrc = isK ? d_gK : d_gV;
    float* rec = isK ? d_recK : d_recV;
    const int ne = n * Ee + e;
    float y = init[(e * Ll + l) * 64 + dd];
    rec[(ne * REC_T + l) * 64 + dd] = y;
    const float* Arow = d_A + ne * Tt;
    const float* grow = gsrc + ne * Tt * 64;
    float* rrow = rec + (ne * REC_T + Ll) * 64;
    #pragma unroll 4
    for (int m = 0; m < M_CH; m++) {
        int t = m * Ll + l;
        y = Arow[t] * y + grow[t * 64 + dd];
        rrow[t * 64 + dd] = y;
    }
}

// ---------------------------------------------------------------------------
// Attention: one block per token (n,t); all H=8 heads share the same
// 128-slot key/value window (E=4 experts x L=32 positions).
// ---------------------------------------------------------------------------
__global__ void __launch_bounds__(256) attn_kernel() {
    extern __shared__ float smem[];
    float* qs = smem;                      // 512
    float* Ks = qs + Hh * DKc;             // 128*65 (padded rows)
    float* Vs = Ks + 128 * 65;             // 128*65
    float* sc = Vs + 128 * 65;             // 8*128
    const int token = blockIdx.x;
    const int n = token / Tt, t = token % Tt;
    const int tid = threadIdx.x;

    qs[tid]       = d_Q[token * 512 + tid];
    qs[tid + 256] = d_Q[token * 512 + tid + 256];

    for (int i = tid; i < 128 * 64; i += 256) {
        int j = i >> 6, dd = i & 63;
        int e = j >> 5;
        int pos = t + (j & 31) + 1;                 // <= 2079 < REC_T
        int off = ((n * Ee + e) * REC_T + pos) * 64 + dd;
        Ks[j * 65 + dd] = d_recK[off];
        Vs[j * 65 + dd] = d_recV[off];
    }
    __syncthreads();

    // scores: 8 heads x 128 slots = 1024 tasks
    #pragma unroll
    for (int r = 0; r < 4; r++) {
        int task = tid + r * 256;
        int h = task >> 7, j = task & 127;
        const float* qrow = qs + h * 64;
        const float* krow = Ks + j * 65;
        float s = 0.f;
        #pragma unroll
        for (int d = 0; d < 64; d++) s += qrow[d] * krow[d];
        sc[h * 128 + j] = s * 0.125f;               // 1/sqrt(64)
    }
    __syncthreads();

    // softmax over 128 slots: warp w handles head h=w
    {
        int h = tid >> 5, lane = tid & 31;
        float v0 = sc[h * 128 + lane];
        float v1 = sc[h * 128 + lane + 32];
        float v2 = sc[h * 128 + lane + 64];
        float v3 = sc[h * 128 + lane + 96];
        float mx = fmaxf(fmaxf(v0, v1), fmaxf(v2, v3));
        #pragma unroll
        for (int o = 16; o; o >>= 1) mx = fmaxf(mx, __shfl_xor_sync(0xffffffffu, mx, o));
        float e0 = expf(v0 - mx), e1 = expf(v1 - mx);
        float e2 = expf(v2 - mx), e3 = expf(v3 - mx);
        float ssum = e0 + e1 + e2 + e3;
        #pragma unroll
        for (int o = 16; o; o >>= 1) ssum += __shfl_xor_sync(0xffffffffu, ssum, o);
        float inv = 1.f / ssum;
        sc[h * 128 + lane]      = e0 * inv;
        sc[h * 128 + lane + 32] = e1 * inv;
        sc[h * 128 + lane + 64] = e2 * inv;
        sc[h * 128 + lane + 96] = e3 * inv;
    }
    __syncthreads();

    // output: 8 heads x 64 dims = 512 outputs
    #pragma unroll
    for (int r = 0; r < 2; r++) {
        int o = tid + r * 256;
        int h = o >> 6, dd = o & 63;
        const float* arow = sc + h * 128;
        float acc = 0.f;
        #pragma unroll 4
        for (int j = 0; j < 128; j++) acc += arow[j] * Vs[j * 65 + dd];
        d_Y[token * 512 + o] = acc;
    }
}

// ---------------------------------------------------------------------------
extern "C" void kernel_launch(void* const* d_in, const int* in_sizes, int n_in,
                              void* d_out, int out_size) {
    const float* X  = (const float*)d_in[0];
    const float* wG = (const float*)d_in[1];
    const float* bG = (const float*)d_in[2];
    const float* wK = (const float*)d_in[3];
    const float* wV = (const float*)d_in[4];
    const float* wQ = (const float*)d_in[5];
    const float* wO = (const float*)d_in[6];
    const float* iK = (const float*)d_in[7];
    const float* iV = (const float*)d_in[8];
    float* out = (float*)d_out;

    float *pK, *pV, *pQ, *pY;
    cudaGetSymbolAddress((void**)&pK, d_K);
    cudaGetSymbolAddress((void**)&pV, d_V);
    cudaGetSymbolAddress((void**)&pQ, d_Q);
    cudaGetSymbolAddress((void**)&pY, d_Y);

    // Projections: C = X * W^T  (W flattened row-major (out_features, DM))
    gemm128<true><<<dim3(4, 32), 256>>>(X, wK, pK, NT, Hh * DKc, DMc);
    gemm128<true><<<dim3(4, 32), 256>>>(X, wV, pV, NT, Hh * DVc, DMc);
    gemm128<true><<<dim3(4, 32), 256>>>(X, wQ, pQ, NT, Hh * DKc, DMc);
    g_kernel<<<NT / 8, 256>>>(X, wG, bG);

    gated_kernel<<<Nn * Ee * Tt, 128>>>();
    scan_kernel<<<Nn * Ee * Ll, 128>>>(iK, iV);

    static const size_t attn_smem = (512 + 2 * 128 * 65 + 8 * 128) * sizeof(float);
    cudaFuncSetAttribute(attn_kernel, cudaFuncAttributeMaxDynamicSharedMemorySize,
                         (int)attn_smem);
    attn_kernel<<<NT, 256, attn_smem>>>();

    // Output: out = Y * w_O  (w_O stored (512, 1024) row-major, not transposed)
    gemm128<false><<<dim3(8, 32), 256>>>(pY, wO, out, NT, DMc, Hh * DVc);
}

// round 6
// speedup vs baseline: 3.1763x; 1.1522x over previous
#include <cuda_runtime.h>
#include <math.h>
#include <stdint.h>

// Problem constants
#define Nn 2
#define Tt 2048
#define DMc 1024
#define Hh 8
#define Ee 4
#define Ll 32
#define DKc 64
#define DVc 64
#define NT (Nn*Tt)           // 4096 tokens
#define REC_T (Tt+Ll)        // 2080 rec positions per (n,e)
#define M_CH (Tt/Ll)         // 64 chunks

// Scratch (allocation-free rule: __device__ globals)
__device__ float d_K[NT*Hh*DKc];       // (token, h*64+d)
__device__ float d_V[NT*Hh*DVc];
__device__ float d_Q[NT*Hh*DKc];
__device__ float d_Gsig[NT*Hh*Ee];     // (token, h*4+e) POST-sigmoid
__device__ float d_A[Nn*Ee*Tt];        // (n,e,t)
__device__ float d_gK[Nn*Ee*Tt*DKc];   // (n,e,t,d)
__device__ float d_gV[Nn*Ee*Tt*DVc];
__device__ float d_recK[Nn*Ee*REC_T*DKc]; // (n,e,pos,d), pos 0..L-1 = init
__device__ float d_recV[Nn*Ee*REC_T*DVc];
__device__ float d_Y[NT*Hh*DVc];       // (token, h*64+d)

// ---------------------------------------------------------------------------
// tf32 helpers
// ---------------------------------------------------------------------------
__device__ __forceinline__ float tf32r(float x) {
    uint32_t u;
    asm("cvt.rna.tf32.f32 %0, %1;" : "=r"(u) : "f"(x));
    return __uint_as_float(u);
}

__device__ __forceinline__ void mma_tf32(float* c, const uint32_t* a, const uint32_t* b) {
    asm volatile("mma.sync.aligned.m16n8k8.row.col.f32.tf32.tf32.f32 "
        "{%0,%1,%2,%3}, {%4,%5,%6,%7}, {%8,%9}, {%0,%1,%2,%3};"
        : "+f"(c[0]), "+f"(c[1]), "+f"(c[2]), "+f"(c[3])
        : "r"(a[0]), "r"(a[1]), "r"(a[2]), "r"(a[3]), "r"(b[0]), "r"(b[1]));
}

// ---------------------------------------------------------------------------
// 3xTF32 tensor-core GEMM, 128x128x16 tile, 256 threads, double-buffered.
//  BT=true : C[M,Ncol] = A[M,K] * B^T,  B stored (Ncol,K) row-major
//  BT=false: C[M,Ncol] = A[M,K] * B,    B stored (K,Ncol) row-major
// Requires M%128==0, Ncol%128==0, K%16==0 (true for all uses here).
// smem planes (hi/lo split precomputed at store time):
//   Ah/Al/Bh/Bl: [2 buf][16 k][132 mn]
// ---------------------------------------------------------------------------
#define SMS (2*16*132)
#define GEMM_SMEM (4*SMS*4)   // bytes = 67584

template<bool BT>
__global__ void __launch_bounds__(256) gemm_tf32(const float* __restrict__ A,
                                                 const float* __restrict__ B,
                                                 float* __restrict__ C,
                                                 int M, int Ncol, int K) {
    extern __shared__ float sm[];
    float* Ah = sm;
    float* Al = Ah + SMS;
    float* Bh = Al + SMS;
    float* Bl = Bh + SMS;

    const int tid = threadIdx.x;
    const int warp = tid >> 5, lane = tid & 31;
    const int wm = (warp >> 2) * 64;       // 0 / 64
    const int wn = (warp & 3) * 32;        // 0 / 32 / 64 / 96
    const int bm = blockIdx.y * 128, bn = blockIdx.x * 128;

    // loader indexing: A and BT-B: 128 rows x 4 float4 along K
    const int r0 = tid >> 2, q0 = tid & 3;   // + second row r0+64
    // !BT B loader: 16 k-rows x 32 float4 cols
    const int kkb0 = tid >> 5, nb0 = tid & 31;

    float4 ra0, ra1, rb0, rb1;

    auto fetch = [&](int k0) {
        ra0 = *(const float4*)(A + (size_t)(bm + r0) * K + k0 + q0 * 4);
        ra1 = *(const float4*)(A + (size_t)(bm + r0 + 64) * K + k0 + q0 * 4);
        if (BT) {
            rb0 = *(const float4*)(B + (size_t)(bn + r0) * K + k0 + q0 * 4);
            rb1 = *(const float4*)(B + (size_t)(bn + r0 + 64) * K + k0 + q0 * 4);
        } else {
            rb0 = *(const float4*)(B + (size_t)(k0 + kkb0) * Ncol + bn + nb0 * 4);
            rb1 = *(const float4*)(B + (size_t)(k0 + kkb0 + 8) * Ncol + bn + nb0 * 4);
        }
    };

    auto putA = [&](float* H, float* L, int kk, int m, float x) {
        float h = tf32r(x);
        H[kk * 132 + m] = h;
        L[kk * 132 + m] = tf32r(x - h);
    };

    auto store = [&](int b) {
        float* AhB = Ah + b * (16 * 132);
        float* AlB = Al + b * (16 * 132);
        float* BhB = Bh + b * (16 * 132);
        float* BlB = Bl + b * (16 * 132);
        const float av0[4] = {ra0.x, ra0.y, ra0.z, ra0.w};
        const float av1[4] = {ra1.x, ra1.y, ra1.z, ra1.w};
        #pragma unroll
        for (int j = 0; j < 4; j++) {
            putA(AhB, AlB, q0 * 4 + j, r0,      av0[j]);
            putA(AhB, AlB, q0 * 4 + j, r0 + 64, av1[j]);
        }
        if (BT) {
            const float bv0[4] = {rb0.x, rb0.y, rb0.z, rb0.w};
            const float bv1[4] = {rb1.x, rb1.y, rb1.z, rb1.w};
            #pragma unroll
            for (int j = 0; j < 4; j++) {
                putA(BhB, BlB, q0 * 4 + j, r0,      bv0[j]);
                putA(BhB, BlB, q0 * 4 + j, r0 + 64, bv1[j]);
            }
        } else {
            const float bv0[4] = {rb0.x, rb0.y, rb0.z, rb0.w};
            const float bv1[4] = {rb1.x, rb1.y, rb1.z, rb1.w};
            #pragma unroll
            for (int j = 0; j < 4; j++) {
                putA(BhB, BlB, kkb0,     nb0 * 4 + j, bv0[j]);
                putA(BhB, BlB, kkb0 + 8, nb0 * 4 + j, bv1[j]);
            }
        }
    };

    float acc[4][4][4] = {};   // [mt][nt][creg]

    auto compute = [&](int b) {
        const float* AhB = Ah + b * (16 * 132);
        const float* AlB = Al + b * (16 * 132);
        const float* BhB = Bh + b * (16 * 132);
        const float* BlB = Bl + b * (16 * 132);
        #pragma unroll
        for (int ks = 0; ks < 16; ks += 8) {
            const int k0 = ks + (lane & 3);
            uint32_t ah[4][4], al[4][4], bh[4][2], bl[4][2];
            #pragma unroll
            for (int mt = 0; mt < 4; mt++) {
                int row = wm + mt * 16 + (lane >> 2);
                ah[mt][0] = __float_as_uint(AhB[k0 * 132 + row]);
                ah[mt][1] = __float_as_uint(AhB[k0 * 132 + row + 8]);
                ah[mt][2] = __float_as_uint(AhB[(k0 + 4) * 132 + row]);
                ah[mt][3] = __float_as_uint(AhB[(k0 + 4) * 132 + row + 8]);
                al[mt][0] = __float_as_uint(AlB[k0 * 132 + row]);
                al[mt][1] = __float_as_uint(AlB[k0 * 132 + row + 8]);
                al[mt][2] = __float_as_uint(AlB[(k0 + 4) * 132 + row]);
                al[mt][3] = __float_as_uint(AlB[(k0 + 4) * 132 + row + 8]);
            }
            #pragma unroll
            for (int nt = 0; nt < 4; nt++) {
                int col = wn + nt * 8 + (lane >> 2);
                bh[nt][0] = __float_as_uint(BhB[k0 * 132 + col]);
                bh[nt][1] = __float_as_uint(BhB[(k0 + 4) * 132 + col]);
                bl[nt][0] = __float_as_uint(BlB[k0 * 132 + col]);
                bl[nt][1] = __float_as_uint(BlB[(k0 + 4) * 132 + col]);
            }
            #pragma unroll
            for (int mt = 0; mt < 4; mt++)
                #pragma unroll
                for (int nt = 0; nt < 4; nt++) {
                    mma_tf32(acc[mt][nt], ah[mt], bh[nt]);
                    mma_tf32(acc[mt][nt], ah[mt], bl[nt]);
                    mma_tf32(acc[mt][nt], al[mt], bh[nt]);
                }
        }
    };

    fetch(0);
    store(0);
    __syncthreads();
    int buf = 0;
    const int nk = K / 16;
    for (int kt = 1; kt < nk; kt++) {
        fetch(kt * 16);
        compute(buf);
        store(buf ^ 1);
        __syncthreads();
        buf ^= 1;
    }
    compute(buf);

    // Epilogue: mma C-fragment layout
    #pragma unroll
    for (int mt = 0; mt < 4; mt++) {
        int row = bm + wm + mt * 16 + (lane >> 2);
        #pragma unroll
        for (int nt = 0; nt < 4; nt++) {
            int col = bn + wn + nt * 8 + (lane & 3) * 2;
            float2 lo = {acc[mt][nt][0], acc[mt][nt][1]};
            float2 hi = {acc[mt][nt][2], acc[mt][nt][3]};
            *(float2*)(C + (size_t)row * Ncol + col) = lo;
            *(float2*)(C + (size_t)(row + 8) * Ncol + col) = hi;
        }
    }
}

// ---------------------------------------------------------------------------
// G projection + bias + sigmoid.
// ---------------------------------------------------------------------------
__global__ void __launch_bounds__(256) g_kernel(const float* __restrict__ X,
                                                const float* __restrict__ wG,
                                                const float* __restrict__ bG) {
    __shared__ float xs[8][1024];
    const int tid = threadIdx.x;
    const int token0 = blockIdx.x * 8;
    #pragma unroll
    for (int i = 0; i < 8; i++) {
        int idx = tid + i * 256;              // float4 index 0..2047
        int tok = idx >> 8, c4 = idx & 255;
        *(float4*)&xs[tok][c4 * 4] =
            *(const float4*)(X + (size_t)(token0 + tok) * DMc + c4 * 4);
    }
    __syncthreads();

    const int w = tid >> 5, lane = tid & 31;
    float acc[4][8] = {};
    #pragma unroll 4
    for (int j = 0; j < 32; j++) {
        int k = j * 32 + lane;
        float wv[4];
        #pragma unroll
        for (int o = 0; o < 4; o++)
            wv[o] = wG[(size_t)(w * 4 + o) * DMc + k];
        #pragma unroll
        for (int tok = 0; tok < 8; tok++) {
            float xv = xs[tok][k];
            #pragma unroll
            for (int o = 0; o < 4; o++)
                acc[o][tok] += wv[o] * xv;
        }
    }
    #pragma unroll
    for (int o = 0; o < 4; o++) {
        float bias = bG[w * 4 + o];
        #pragma unroll
        for (int tok = 0; tok < 8; tok++) {
            float v = acc[o][tok];
            #pragma unroll
            for (int off = 16; off; off >>= 1)
                v += __shfl_xor_sync(0xffffffffu, v, off);
            if (lane == 0)
                d_Gsig[(size_t)(token0 + tok) * (Hh * Ee) + w * 4 + o] =
                    1.f / (1.f + expf(-(v + bias)));
        }
    }
}

// ---------------------------------------------------------------------------
// Gating: per (n,e,t) compute gated_K, gated_V (sum over heads), and A.
// ---------------------------------------------------------------------------
__global__ void __launch_bounds__(128) gated_kernel() {
    const int blk = blockIdx.x;
    const int t = blk % Tt;
    const int e = (blk / Tt) % Ee;
    const int n = blk / (Tt * Ee);
    const int token = n * Tt + t;
    __shared__ float g[Hh];
    const int tid = threadIdx.x;
    if (tid < Hh)
        g[tid] = d_Gsig[token * (Hh * Ee) + tid * Ee + e];
    __syncthreads();
    if (tid < 64) {
        float s = 0.f;
        #pragma unroll
        for (int h = 0; h < Hh; h++) s += g[h] * d_K[token * (Hh * DKc) + h * DKc + tid];
        d_gK[((n * Ee + e) * Tt + t) * DKc + tid] = s;
    } else {
        int dd = tid - 64;
        float s = 0.f;
        #pragma unroll
        for (int h = 0; h < Hh; h++) s += g[h] * d_V[token * (Hh * DVc) + h * DVc + dd];
        d_gV[((n * Ee + e) * Tt + t) * DVc + dd] = s;
    }
    if (tid == 0) {
        float sa = 0.f;
        #pragma unroll
        for (int h = 0; h < Hh; h++) sa += g[h];
        d_A[(n * Ee + e) * Tt + t] = 1.f - sa;
    }
}

// ---------------------------------------------------------------------------
// Scan: L-strided recurrence rec[t] = A[t]*rec[t-L] + gated[t].
// ---------------------------------------------------------------------------
__global__ void __launch_bounds__(128) scan_kernel(const float* __restrict__ initK,
                                                   const float* __restrict__ initV) {
    const int b = blockIdx.x;             // Nn*Ee*Ll = 256 blocks
    const int l = b % Ll;
    const int e = (b / Ll) % Ee;
    const int n = b / (Ll * Ee);
    const int d = threadIdx.x;
    const bool isK = d < 64;
    const int dd = isK ? d : d - 64;
    const float* init = isK ? initK : initV;
    const float* gsrc = isK ? d_gK : d_gV;
    float* rec = isK ? d_recK : d_recV;
    const int ne = n * Ee + e;
    float y = init[(e * Ll + l) * 64 + dd];
    rec[(ne * REC_T + l) * 64 + dd] = y;
    const float* Arow = d_A + ne * Tt;
    const float* grow = gsrc + ne * Tt * 64;
    float* rrow = rec + (ne * REC_T + Ll) * 64;
    #pragma unroll 4
    for (int m = 0; m < M_CH; m++) {
        int t = m * Ll + l;
        y = Arow[t] * y + grow[t * 64 + dd];
        rrow[t * 64 + dd] = y;
    }
}

// ---------------------------------------------------------------------------
// Attention: one block per token (n,t); all H=8 heads share the same
// 128-slot key/value window (E=4 experts x L=32 positions).
// ---------------------------------------------------------------------------
__global__ void __launch_bounds__(256) attn_kernel() {
    extern __shared__ float smem[];
    float* qs = smem;                      // 512
    float* Ks = qs + Hh * DKc;             // 128*65 (padded rows)
    float* Vs = Ks + 128 * 65;             // 128*65
    float* sc = Vs + 128 * 65;             // 8*128
    const int token = blockIdx.x;
    const int n = token / Tt, t = token % Tt;
    const int tid = threadIdx.x;

    qs[tid]       = d_Q[token * 512 + tid];
    qs[tid + 256] = d_Q[token * 512 + tid + 256];

    for (int i = tid; i < 128 * 64; i += 256) {
        int j = i >> 6, dd = i & 63;
        int e = j >> 5;
        int pos = t + (j & 31) + 1;                 // <= 2079 < REC_T
        int off = ((n * Ee + e) * REC_T + pos) * 64 + dd;
        Ks[j * 65 + dd] = d_recK[off];
        Vs[j * 65 + dd] = d_recV[off];
    }
    __syncthreads();

    // scores: 8 heads x 128 slots = 1024 tasks
    #pragma unroll
    for (int r = 0; r < 4; r++) {
        int task = tid + r * 256;
        int h = task >> 7, j = task & 127;
        const float* qrow = qs + h * 64;
        const float* krow = Ks + j * 65;
        float s = 0.f;
        #pragma unroll
        for (int d = 0; d < 64; d++) s += qrow[d] * krow[d];
        sc[h * 128 + j] = s * 0.125f;               // 1/sqrt(64)
    }
    __syncthreads();

    // softmax over 128 slots: warp w handles head h=w
    {
        int h = tid >> 5, lane = tid & 31;
        float v0 = sc[h * 128 + lane];
        float v1 = sc[h * 128 + lane + 32];
        float v2 = sc[h * 128 + lane + 64];
        float v3 = sc[h * 128 + lane + 96];
        float mx = fmaxf(fmaxf(v0, v1), fmaxf(v2, v3));
        #pragma unroll
        for (int o = 16; o; o >>= 1) mx = fmaxf(mx, __shfl_xor_sync(0xffffffffu, mx, o));
        float e0 = expf(v0 - mx), e1 = expf(v1 - mx);
        float e2 = expf(v2 - mx), e3 = expf(v3 - mx);
        float ssum = e0 + e1 + e2 + e3;
        #pragma unroll
        for (int o = 16; o; o >>= 1) ssum += __shfl_xor_sync(0xffffffffu, ssum, o);
        float inv = 1.f / ssum;
        sc[h * 128 + lane]      = e0 * inv;
        sc[h * 128 + lane + 32] = e1 * inv;
        sc[h * 128 + lane + 64] = e2 * inv;
        sc[h * 128 + lane + 96] = e3 * inv;
    }
    __syncthreads();

    // output: 8 heads x 64 dims = 512 outputs
    #pragma unroll
    for (int r = 0; r < 2; r++) {
        int o = tid + r * 256;
        int h = o >> 6, dd = o & 63;
        const float* arow = sc + h * 128;
        float acc = 0.f;
        #pragma unroll 4
        for (int j = 0; j < 128; j++) acc += arow[j] * Vs[j * 65 + dd];
        d_Y[token * 512 + o] = acc;
    }
}

// ---------------------------------------------------------------------------
extern "C" void kernel_launch(void* const* d_in, const int* in_sizes, int n_in,
                              void* d_out, int out_size) {
    const float* X  = (const float*)d_in[0];
    const float* wG = (const float*)d_in[1];
    const float* bG = (const float*)d_in[2];
    const float* wK = (const float*)d_in[3];
    const float* wV = (const float*)d_in[4];
    const float* wQ = (const float*)d_in[5];
    const float* wO = (const float*)d_in[6];
    const float* iK = (const float*)d_in[7];
    const float* iV = (const float*)d_in[8];
    float* out = (float*)d_out;

    float *pK, *pV, *pQ, *pY;
    cudaGetSymbolAddress((void**)&pK, d_K);
    cudaGetSymbolAddress((void**)&pV, d_V);
    cudaGetSymbolAddress((void**)&pQ, d_Q);
    cudaGetSymbolAddress((void**)&pY, d_Y);

    cudaFuncSetAttribute(gemm_tf32<true>,  cudaFuncAttributeMaxDynamicSharedMemorySize, GEMM_SMEM);
    cudaFuncSetAttribute(gemm_tf32<false>, cudaFuncAttributeMaxDynamicSharedMemorySize, GEMM_SMEM);

    // Projections: C = X * W^T  (W flattened row-major (out_features, DM))
    gemm_tf32<true><<<dim3(4, 32), 256, GEMM_SMEM>>>(X, wK, pK, NT, Hh * DKc, DMc);
    gemm_tf32<true><<<dim3(4, 32), 256, GEMM_SMEM>>>(X, wV, pV, NT, Hh * DVc, DMc);
    gemm_tf32<true><<<dim3(4, 32), 256, GEMM_SMEM>>>(X, wQ, pQ, NT, Hh * DKc, DMc);
    g_kernel<<<NT / 8, 256>>>(X, wG, bG);

    gated_kernel<<<Nn * Ee * Tt, 128>>>();
    scan_kernel<<<Nn * Ee * Ll, 128>>>(iK, iV);

    static const size_t attn_smem = (512 + 2 * 128 * 65 + 8 * 128) * sizeof(float);
    cudaFuncSetAttribute(attn_kernel, cudaFuncAttributeMaxDynamicSharedMemorySize,
                         (int)attn_smem);
    attn_kernel<<<NT, 256, attn_smem>>>();

    // Output: out = Y * w_O  (w_O stored (512, 1024) row-major, not transposed)
    gemm_tf32<false><<<dim3(8, 32), 256, GEMM_SMEM>>>(pY, wO, out, NT, DMc, Hh * DVc);
}

// round 8
// speedup vs baseline: 3.2075x; 1.0098x over previous
#include <cuda_runtime.h>
#include <math.h>
#include <stdint.h>

// Problem constants
#define Nn 2
#define Tt 2048
#define DMc 1024
#define Hh 8
#define Ee 4
#define Ll 32
#define DKc 64
#define DVc 64
#define NT (Nn*Tt)           // 4096 tokens
#define REC_T (Tt+Ll)        // 2080 rec positions per (n,e)
#define M_CH (Tt/Ll)         // 64 chunks

// Scratch (allocation-free rule: __device__ globals)
__device__ float d_K[NT*Hh*DKc];       // (token, h*64+d)
__device__ float d_V[NT*Hh*DVc];
__device__ float d_Q[NT*Hh*DKc];
__device__ float d_Gsig[NT*Hh*Ee];     // (token, h*4+e) POST-sigmoid
__device__ float d_A[Nn*Ee*Tt];        // (n,e,t)
__device__ float d_gK[Nn*Ee*Tt*DKc];   // (n,e,t,d)
__device__ float d_gV[Nn*Ee*Tt*DVc];
__device__ float d_recK[Nn*Ee*REC_T*DKc]; // (n,e,pos,d), pos 0..L-1 = init
__device__ float d_recV[Nn*Ee*REC_T*DVc];

// Pre-split tf32 hi/lo planes
__device__ float d_Xh[NT*DMc],  d_Xl[NT*DMc];
__device__ float d_wKh[512*1024], d_wKl[512*1024];
__device__ float d_wVh[512*1024], d_wVl[512*1024];
__device__ float d_wQh[512*1024], d_wQl[512*1024];
__device__ float d_wOh[1024*512], d_wOl[1024*512];   // wO transposed + split
__device__ float d_Yh[NT*Hh*DVc], d_Yl[NT*Hh*DVc];

// ---------------------------------------------------------------------------
// helpers
// ---------------------------------------------------------------------------
__device__ __forceinline__ uint32_t smem_u32(const void* p) {
    uint32_t a;
    asm("{ .reg .u64 t; cvta.to.shared.u64 t, %1; cvt.u32.u64 %0, t; }"
        : "=r"(a) : "l"(p));
    return a;
}

__device__ __forceinline__ float tf32r(float x) {
    uint32_t u;
    asm("cvt.rna.tf32.f32 %0, %1;" : "=r"(u) : "f"(x));
    return __uint_as_float(u);
}

__device__ __forceinline__ void mma_tf32(float* c, const uint32_t* a, const uint32_t* b) {
    asm volatile("mma.sync.aligned.m16n8k8.row.col.f32.tf32.tf32.f32 "
        "{%0,%1,%2,%3}, {%4,%5,%6,%7}, {%8,%9}, {%0,%1,%2,%3};"
        : "+f"(c[0]), "+f"(c[1]), "+f"(c[2]), "+f"(c[3])
        : "r"(a[0]), "r"(a[1]), "r"(a[2]), "r"(a[3]), "r"(b[0]), "r"(b[1]));
}

__device__ __forceinline__ void cp16(uint32_t dst, const void* src) {
    asm volatile("cp.async.cg.shared.global [%0], [%1], 16;" :: "r"(dst), "l"(src));
}
#define CP_COMMIT() asm volatile("cp.async.commit_group;" ::: "memory")
#define CP_WAIT1()  asm volatile("cp.async.wait_group 1;" ::: "memory")
#define CP_WAIT0()  asm volatile("cp.async.wait_group 0;" ::: "memory")

// ---------------------------------------------------------------------------
// 3xTF32 GEMM on pre-split planes: C[128x128] tile at (bm, bn).
//  A planes: [Mtot, K] row-major; B planes: [Ntot, K] row-major (C = A * B^T).
// 256 threads, warp tile 64x32. smem: per stage 4 planes of 128 rows x 20
// floats (16 data + 4 pad -> conflict-free fragment loads). cp.async 2-stage.
// ---------------------------------------------------------------------------
#define PSTR (128*20)                 // floats per plane
#define GSM3 (2*4*PSTR*4)             // bytes = 81920

__device__ __forceinline__ void gemm3_tile(const float* __restrict__ Ah,
                                           const float* __restrict__ Al,
                                           const float* __restrict__ Bh,
                                           const float* __restrict__ Bl,
                                           float* __restrict__ C,
                                           int Ncol, int K, int bm, int bn) {
    extern __shared__ float sm3[];
    const uint32_t sbase = smem_u32(sm3);
    const int tid = threadIdx.x;
    const int warp = tid >> 5, lane = tid & 31;
    const int wm = (warp >> 2) * 64;      // 0 / 64
    const int wn = (warp & 3) * 32;       // 0..96
    const int r = lane >> 2, cf = lane & 3;

    const int seg0 = tid, seg1 = tid + 256;      // 512 16B-segments per plane
    const int row0 = seg0 >> 2, q0 = seg0 & 3;
    const int row1 = seg1 >> 2, q1 = seg1 & 3;

    auto copy = [&](int kt, int buf) {
        #pragma unroll
        for (int p = 0; p < 4; p++) {
            const float* src = (p == 0) ? Ah : (p == 1) ? Al : (p == 2) ? Bh : Bl;
            const int rb = (p < 2) ? bm : bn;
            uint32_t db = sbase + (uint32_t)((buf * 4 + p) * PSTR) * 4u;
            cp16(db + (uint32_t)(row0 * 20 + q0 * 4) * 4u,
                 src + (size_t)(rb + row0) * K + kt * 16 + q0 * 4);
            cp16(db + (uint32_t)(row1 * 20 + q1 * 4) * 4u,
                 src + (size_t)(rb + row1) * K + kt * 16 + q1 * 4);
        }
        CP_COMMIT();
    };

    float acc[4][4][4] = {};

    auto compute = [&](int buf) {
        const float* pAh = sm3 + (buf * 4 + 0) * PSTR;
        const float* pAl = sm3 + (buf * 4 + 1) * PSTR;
        const float* pBh = sm3 + (buf * 4 + 2) * PSTR;
        const float* pBl = sm3 + (buf * 4 + 3) * PSTR;
        #pragma unroll
        for (int ks = 0; ks < 16; ks += 8) {
            uint32_t ah[4][4], al[4][4], bh[4][2], bl[4][2];
            #pragma unroll
            for (int mt = 0; mt < 4; mt++) {
                int o = (wm + mt * 16 + r) * 20 + ks + cf;
                ah[mt][0] = __float_as_uint(pAh[o]);
                ah[mt][1] = __float_as_uint(pAh[o + 160]);      // +8 rows
                ah[mt][2] = __float_as_uint(pAh[o + 4]);
                ah[mt][3] = __float_as_uint(pAh[o + 164]);
                al[mt][0] = __float_as_uint(pAl[o]);
                al[mt][1] = __float_as_uint(pAl[o + 160]);
                al[mt][2] = __float_as_uint(pAl[o + 4]);
                al[mt][3] = __float_as_uint(pAl[o + 164]);
            }
            #pragma unroll
            for (int nt = 0; nt < 4; nt++) {
                int o = (wn + nt * 8 + r) * 20 + ks + cf;
                bh[nt][0] = __float_as_uint(pBh[o]);
                bh[nt][1] = __float_as_uint(pBh[o + 4]);
                bl[nt][0] = __float_as_uint(pBl[o]);
                bl[nt][1] = __float_as_uint(pBl[o + 4]);
            }
            #pragma unroll
            for (int mt = 0; mt < 4; mt++)
                #pragma unroll
                for (int nt = 0; nt < 4; nt++) {
                    mma_tf32(acc[mt][nt], ah[mt], bh[nt]);
                    mma_tf32(acc[mt][nt], ah[mt], bl[nt]);
                    mma_tf32(acc[mt][nt], al[mt], bh[nt]);
                }
        }
    };

    const int NK = K / 16;
    copy(0, 0);
    for (int kt = 0; kt < NK; kt++) {
        if (kt + 1 < NK) {
            copy(kt + 1, (kt + 1) & 1);
            CP_WAIT1();
        } else {
            CP_WAIT0();
        }
        __syncthreads();
        compute(kt & 1);
        __syncthreads();
    }

    // Epilogue: mma C-fragment layout, float2 stores
    #pragma unroll
    for (int mt = 0; mt < 4; mt++) {
        int row = bm + wm + mt * 16 + r;
        #pragma unroll
        for (int nt = 0; nt < 4; nt++) {
            int col = bn + wn + nt * 8 + cf * 2;
            float2 lo = {acc[mt][nt][0], acc[mt][nt][1]};
            float2 hi = {acc[mt][nt][2], acc[mt][nt][3]};
            *(float2*)(C + (size_t)row * Ncol + col) = lo;
            *(float2*)(C + (size_t)(row + 8) * Ncol + col) = hi;
        }
    }
}

// K/V/Q projections fused via blockIdx.z
__global__ void __launch_bounds__(256) gemm_kvq() {
    const float *Bh, *Bl;
    float* C;
    if (blockIdx.z == 0)      { Bh = d_wKh; Bl = d_wKl; C = d_K; }
    else if (blockIdx.z == 1) { Bh = d_wVh; Bl = d_wVl; C = d_V; }
    else                      { Bh = d_wQh; Bl = d_wQl; C = d_Q; }
    gemm3_tile(d_Xh, d_Xl, Bh, Bl, C, 512, 1024,
               blockIdx.y * 128, blockIdx.x * 128);
}

// Output GEMM: out = Y * wO = Y * (wOT)^T
__global__ void __launch_bounds__(256) gemm_out(float* __restrict__ out) {
    gemm3_tile(d_Yh, d_Yl, d_wOh, d_wOl, out, 1024, 512,
               blockIdx.y * 128, blockIdx.x * 128);
}

// ---------------------------------------------------------------------------
// One-shot weight split: wK/wV/wQ -> tf32 hi/lo planes (by blockIdx.y)
// ---------------------------------------------------------------------------
__global__ void __launch_bounds__(256) split_w(const float* __restrict__ wK,
                                               const float* __restrict__ wV,
                                               const float* __restrict__ wQ) {
    const float* src = (blockIdx.y == 0) ? wK : (blockIdx.y == 1) ? wV : wQ;
    float* dh = (blockIdx.y == 0) ? d_wKh : (blockIdx.y == 1) ? d_wVh : d_wQh;
    float* dl = (blockIdx.y == 0) ? d_wKl : (blockIdx.y == 1) ? d_wVl : d_wQl;
    int i = blockIdx.x * 256 + threadIdx.x;      // float4 index, 131072 total
    float4 v = *(const float4*)(src + (size_t)i * 4);
    float4 h, l;
    h.x = tf32r(v.x); l.x = tf32r(v.x - h.x);
    h.y = tf32r(v.y); l.y = tf32r(v.y - h.y);
    h.z = tf32r(v.z); l.z = tf32r(v.z - h.z);
    h.w = tf32r(v.w); l.w = tf32r(v.w - h.w);
    *(float4*)(dh + (size_t)i * 4) = h;
    *(float4*)(dl + (size_t)i * 4) = l;
}

// wO (512 x 1024 row-major) -> transposed + split (1024 x 512) hi/lo
__global__ void transpose_wo(const float* __restrict__ wo) {
    __shared__ float t[32][33];
    int bx = blockIdx.x * 32;   // over N (1024)
    int by = blockIdx.y * 32;   // over K (512)
    int x = threadIdx.x, y = threadIdx.y;
    #pragma unroll
    for (int j = 0; j < 32; j += 8)
        t[y + j][x] = wo[(size_t)(by + y + j) * 1024 + bx + x];
    __syncthreads();
    #pragma unroll
    for (int j = 0; j < 32; j += 8) {
        float v = t[x][y + j];
        float h = tf32r(v), l = tf32r(v - h);
        d_wOh[(size_t)(bx + y + j) * 512 + by + x] = h;
        d_wOl[(size_t)(bx + y + j) * 512 + by + x] = l;
    }
}

// ---------------------------------------------------------------------------
// G projection + bias + sigmoid; also emits X hi/lo tf32 planes.
// ---------------------------------------------------------------------------
__global__ void __launch_bounds__(256) g_kernel(const float* __restrict__ X,
                                                const float* __restrict__ wG,
                                                const float* __restrict__ bG) {
    __shared__ float xs[8][1024];
    const int tid = threadIdx.x;
    const int token0 = blockIdx.x * 8;
    #pragma unroll
    for (int i = 0; i < 8; i++) {
        int idx = tid + i * 256;              // float4 index 0..2047
        int tok = idx >> 8, c4 = idx & 255;
        float4 v = *(const float4*)(X + (size_t)(token0 + tok) * DMc + c4 * 4);
        *(float4*)&xs[tok][c4 * 4] = v;
        float4 h, l;
        h.x = tf32r(v.x); l.x = tf32r(v.x - h.x);
        h.y = tf32r(v.y); l.y = tf32r(v.y - h.y);
        h.z = tf32r(v.z); l.z = tf32r(v.z - h.z);
        h.w = tf32r(v.w); l.w = tf32r(v.w - h.w);
        size_t o = (size_t)(token0 + tok) * DMc + c4 * 4;
        *(float4*)(d_Xh + o) = h;
        *(float4*)(d_Xl + o) = l;
    }
    __syncthreads();

    const int w = tid >> 5, lane = tid & 31;
    float acc[4][8] = {};
    #pragma unroll 4
    for (int j = 0; j < 32; j++) {
        int k = j * 32 + lane;
        float wv[4];
        #pragma unroll
        for (int o = 0; o < 4; o++)
            wv[o] = wG[(size_t)(w * 4 + o) * DMc + k];
        #pragma unroll
        for (int tok = 0; tok < 8; tok++) {
            float xv = xs[tok][k];
            #pragma unroll
            for (int o = 0; o < 4; o++)
                acc[o][tok] += wv[o] * xv;
        }
    }
    #pragma unroll
    for (int o = 0; o < 4; o++) {
        float bias = bG[w * 4 + o];
        #pragma unroll
        for (int tok = 0; tok < 8; tok++) {
            float v = acc[o][tok];
            #pragma unroll
            for (int off = 16; off; off >>= 1)
                v += __shfl_xor_sync(0xffffffffu, v, off);
            if (lane == 0)
                d_Gsig[(size_t)(token0 + tok) * (Hh * Ee) + w * 4 + o] =
                    1.f / (1.f + expf(-(v + bias)));
        }
    }
}

// ---------------------------------------------------------------------------
// Gating: per (n,e,t) compute gated_K, gated_V (sum over heads), and A.
// ---------------------------------------------------------------------------
__global__ void __launch_bounds__(128) gated_kernel() {
    const int blk = blockIdx.x;
    const int t = blk % Tt;
    const int e = (blk / Tt) % Ee;
    const int n = blk / (Tt * Ee);
    const int token = n * Tt + t;
    __shared__ float g[Hh];
    const int tid = threadIdx.x;
    if (tid < Hh)
        g[tid] = d_Gsig[token * (Hh * Ee) + tid * Ee + e];
    __syncthreads();
    if (tid < 64) {
        float s = 0.f;
        #pragma unroll
        for (int h = 0; h < Hh; h++) s += g[h] * d_K[token * (Hh * DKc) + h * DKc + tid];
        d_gK[((n * Ee + e) * Tt + t) * DKc + tid] = s;
    } else {
        int dd = tid - 64;
        float s = 0.f;
        #pragma unroll
        for (int h = 0; h < Hh; h++) s += g[h] * d_V[token * (Hh * DVc) + h * DVc + dd];
        d_gV[((n * Ee + e) * Tt + t) * DVc + dd] = s;
    }
    if (tid == 0) {
        float sa = 0.f;
        #pragma unroll
        for (int h = 0; h < Hh; h++) sa += g[h];
        d_A[(n * Ee + e) * Tt + t] = 1.f - sa;
    }
}

// ---------------------------------------------------------------------------
// Scan: L-strided recurrence rec[t] = A[t]*rec[t-L] + gated[t].
// ---------------------------------------------------------------------------
__global__ void __launch_bounds__(128) scan_kernel(const float* __restrict__ initK,
                                                   const float* __restrict__ initV) {
    const int b = blockIdx.x;             // Nn*Ee*Ll = 256 blocks
    const int l = b % Ll;
    const int e = (b / Ll) % Ee;
    const int n = b / (Ll * Ee);
    const int d = threadIdx.x;
    const bool isK = d < 64;
    const int dd = isK ? d : d - 64;
    const float* init = isK ? initK : initV;
    const float* gsrc = isK ? d_gK : d_gV;
    float* rec = isK ? d_recK : d_recV;
    const int ne = n * Ee + e;
    float y = init[(e * Ll + l) * 64 + dd];
    rec[(ne * REC_T + l) * 64 + dd] = y;
    const float* Arow = d_A + ne * Tt;
    const float* grow = gsrc + ne * Tt * 64;
    float* rrow = rec + (ne * REC_T + Ll) * 64;
    #pragma unroll 4
    for (int m = 0; m < M_CH; m++) {
        int t = m * Ll + l;
        y = Arow[t] * y + grow[t * 64 + dd];
        rrow[t * 64 + dd] = y;
    }
}

// ---------------------------------------------------------------------------
// Attention: one block per token (n,t); all H=8 heads share the same
// 128-slot key/value window (E=4 experts x L=32 positions).
// Epilogue writes Y directly as tf32 hi/lo planes for the output GEMM.
// ---------------------------------------------------------------------------
__global__ void __launch_bounds__(256) attn_kernel() {
    extern __shared__ float smem[];
    float* qs = smem;                      // 512
    float* Ks = qs + Hh * DKc;             // 128*65 (padded rows)
    float* Vs = Ks + 128 * 65;             // 128*65
    float* sc = Vs + 128 * 65;             // 8*128
    const int token = blockIdx.x;
    const int n = token / Tt, t = token % Tt;
    const int tid = threadIdx.x;

    qs[tid]       = d_Q[token * 512 + tid];
    qs[tid + 256] = d_Q[token * 512 + tid + 256];

    for (int i = tid; i < 128 * 64; i += 256) {
        int j = i >> 6, dd = i & 63;
        int e = j >> 5;
        int pos = t + (j & 31) + 1;                 // <= 2079 < REC_T
        int off = ((n * Ee + e) * REC_T + pos) * 64 + dd;
        Ks[j * 65 + dd] = d_recK[off];
        Vs[j * 65 + dd] = d_recV[off];
    }
    __syncthreads();

    // scores: 8 heads x 128 slots = 1024 tasks
    #pragma unroll
    for (int r = 0; r < 4; r++) {
        int task = tid + r * 256;
        int h = task >> 7, j = task & 127;
        const float* qrow = qs + h * 64;
        const float* krow = Ks + j * 65;
        float s = 0.f;
        #pragma unroll
        for (int d = 0; d < 64; d++) s += qrow[d] * krow[d];
        sc[h * 128 + j] = s * 0.125f;               // 1/sqrt(64)
    }
    __syncthreads();

    // softmax over 128 slots: warp w handles head h=w
    {
        int h = tid >> 5, lane = tid & 31;
        float v0 = sc[h * 128 + lane];
        float v1 = sc[h * 128 + lane + 32];
        float v2 = sc[h * 128 + lane + 64];
        float v3 = sc[h * 128 + lane + 96];
        float mx = fmaxf(fmaxf(v0, v1), fmaxf(v2, v3));
        #pragma unroll
        for (int o = 16; o; o >>= 1) mx = fmaxf(mx, __shfl_xor_sync(0xffffffffu, mx, o));
        float e0 = expf(v0 - mx), e1 = expf(v1 - mx);
        float e2 = expf(v2 - mx), e3 = expf(v3 - mx);
        float ssum = e0 + e1 + e2 + e3;
        #pragma unroll
        for (int o = 16; o; o >>= 1) ssum += __shfl_xor_sync(0xffffffffu, ssum, o);
        float inv = 1.f / ssum;
        sc[h * 128 + lane]      = e0 * inv;
        sc[h * 128 + lane + 32] = e1 * inv;
        sc[h * 128 + lane + 64] = e2 * inv;
        sc[h * 128 + lane + 96] = e3 * inv;
    }
    __syncthreads();

    // output: 8 heads x 64 dims = 512 outputs, split to tf32 hi/lo
    #pragma unroll
    for (int r = 0; r < 2; r++) {
        int o = tid + r * 256;
        int h = o >> 6, dd = o & 63;
        const float* arow = sc + h * 128;
        float acc = 0.f;
        #pragma unroll 4
        for (int j = 0; j < 128; j++) acc += arow[j] * Vs[j * 65 + dd];
        float hpart = tf32r(acc);
        d_Yh[token * 512 + o] = hpart;
        d_Yl[token * 512 + o] = tf32r(acc - hpart);
    }
}

// ---------------------------------------------------------------------------
extern "C" void kernel_launch(void* const* d_in, const int* in_sizes, int n_in,
                              void* d_out, int out_size) {
    const float* X  = (const float*)d_in[0];
    const float* wG = (const float*)d_in[1];
    const float* bG = (const float*)d_in[2];
    const float* wK = (const float*)d_in[3];
    const float* wV = (const float*)d_in[4];
    const float* wQ = (const float*)d_in[5];
    const float* wO = (const float*)d_in[6];
    const float* iK = (const float*)d_in[7];
    const float* iV = (const float*)d_in[8];
    float* out = (float*)d_out;

    cudaFuncSetAttribute(gemm_kvq, cudaFuncAttributeMaxDynamicSharedMemorySize, GSM3);
    cudaFuncSetAttribute(gemm_out, cudaFuncAttributeMaxDynamicSharedMemorySize, GSM3);

    // One-shot operand preparation (splits + transpose)
    split_w<<<dim3(512, 3), 256>>>(wK, wV, wQ);
    transpose_wo<<<dim3(32, 16), dim3(32, 8)>>>(wO);
    g_kernel<<<NT / 8, 256>>>(X, wG, bG);     // also emits d_Xh / d_Xl

    // K/V/Q projections on pre-split planes, fused on grid.z
    gemm_kvq<<<dim3(4, 32, 3), 256, GSM3>>>();

    gated_kernel<<<Nn * Ee * Tt, 128>>>();
    scan_kernel<<<Nn * Ee * Ll, 128>>>(iK, iV);

    static const size_t attn_smem = (512 + 2 * 128 * 65 + 8 * 128) * sizeof(float);
    cudaFuncSetAttribute(attn_kernel, cudaFuncAttributeMaxDynamicSharedMemorySize,
                         (int)attn_smem);
    attn_kernel<<<NT, 256, attn_smem>>>();

    // Output: out = Y * wO = Y * (wOT)^T
    gemm_out<<<dim3(8, 32), 256, GSM3>>>(out);
}

// round 9
// speedup vs baseline: 4.3981x; 1.3712x over previous
#include <cuda_runtime.h>
#include <cuda_bf16.h>
#include <math.h>
#include <stdint.h>

// Problem constants
#define Nn 2
#define Tt 2048
#define DMc 1024
#define Hh 8
#define Ee 4
#define Ll 32
#define DKc 64
#define DVc 64
#define NT (Nn*Tt)           // 4096 tokens
#define REC_T (Tt+Ll)        // 2080 rec positions per (n,e)
#define M_CH (Tt/Ll)         // 64 chunks

typedef __nv_bfloat16 bf16;
typedef __nv_bfloat162 bf162;

// Scratch (allocation-free rule: __device__ globals)
__device__ float d_K[NT*Hh*DKc];       // (token, h*64+d)
__device__ float d_V[NT*Hh*DVc];
__device__ float d_Q[NT*Hh*DKc];
__device__ float d_Gsig[NT*Hh*Ee];     // (token, h*4+e) POST-sigmoid
__device__ float d_A[Nn*Ee*Tt];        // (n,e,t)
__device__ float d_gK[Nn*Ee*Tt*DKc];   // (n,e,t,d)
__device__ float d_gV[Nn*Ee*Tt*DVc];
__device__ float d_recK[Nn*Ee*REC_T*DKc]; // (n,e,pos,d), pos 0..L-1 = init
__device__ float d_recV[Nn*Ee*REC_T*DVc];

// Pre-split bf16 hi/lo planes
__device__ bf16 d_Xh[NT*DMc],    d_Xl[NT*DMc];
__device__ bf16 d_wKh[512*1024], d_wKl[512*1024];
__device__ bf16 d_wVh[512*1024], d_wVl[512*1024];
__device__ bf16 d_wQh[512*1024], d_wQl[512*1024];
__device__ bf16 d_wOh[1024*512], d_wOl[1024*512];   // wO transposed + split
__device__ bf16 d_Yh[NT*Hh*DVc], d_Yl[NT*Hh*DVc];

// ---------------------------------------------------------------------------
// helpers
// ---------------------------------------------------------------------------
__device__ __forceinline__ uint32_t smem_u32(const void* p) {
    uint32_t a;
    asm("{ .reg .u64 t; cvta.to.shared.u64 t, %1; cvt.u32.u64 %0, t; }"
        : "=r"(a) : "l"(p));
    return a;
}

__device__ __forceinline__ void split_bf(float x, bf16& h, bf16& l) {
    h = __float2bfloat16(x);
    l = __float2bfloat16(x - __bfloat162float(h));
}

__device__ __forceinline__ void mma_bf16(float* c, const uint32_t* a, const uint32_t* b) {
    asm volatile("mma.sync.aligned.m16n8k16.row.col.f32.bf16.bf16.f32 "
        "{%0,%1,%2,%3}, {%4,%5,%6,%7}, {%8,%9}, {%0,%1,%2,%3};"
        : "+f"(c[0]), "+f"(c[1]), "+f"(c[2]), "+f"(c[3])
        : "r"(a[0]), "r"(a[1]), "r"(a[2]), "r"(a[3]), "r"(b[0]), "r"(b[1]));
}

__device__ __forceinline__ void cp16(uint32_t dst, const void* src) {
    asm volatile("cp.async.cg.shared.global [%0], [%1], 16;" :: "r"(dst), "l"(src));
}
#define CP_COMMIT() asm volatile("cp.async.commit_group;" ::: "memory")
#define CP_WAIT2()  asm volatile("cp.async.wait_group 2;" ::: "memory")

// ---------------------------------------------------------------------------
// 3x-split bf16 GEMM (m16n8k16): C[128x128] tile at (bm, bn).
//  A planes: [Mtot, K] bf16 row-major; B planes: [Ntot, K] bf16 row-major
//  (C = A * B^T, fp32 accumulate; acc = AhBh + AhBl + AlBh).
// 256 threads, warp tile 64x32. smem: 4-stage ring; per stage 4 planes of
// 128 rows x 12 uint32 (8 data kpairs + 4 pad -> conflict-free frag loads).
// ---------------------------------------------------------------------------
#define SROW 12                        // uint32 per row
#define PLU (128*SROW)                 // uint32 per plane = 1536
#define STGU (4*PLU)                   // uint32 per stage = 6144 (24KB)
#define GSMB (4*STGU*4)                // bytes = 98304 (4 stages)

__device__ __forceinline__ void gemm3_tile(const bf16* __restrict__ Ah,
                                           const bf16* __restrict__ Al,
                                           const bf16* __restrict__ Bh,
                                           const bf16* __restrict__ Bl,
                                           float* __restrict__ C,
                                           int Ncol, int K, int bm, int bn) {
    extern __shared__ uint32_t smu[];
    const uint32_t sbase = smem_u32(smu);
    const int tid = threadIdx.x;
    const int warp = tid >> 5, lane = tid & 31;
    const int wm = (warp >> 2) * 64;      // 0 / 64
    const int wn = (warp & 3) * 32;       // 0..96
    const int r = lane >> 2, cf = lane & 3;

    const int row = tid >> 1, half = tid & 1;   // loader: 1 seg/plane/thread

    auto copy = [&](int kt, int slot) {
        uint32_t db = sbase + (uint32_t)(slot * STGU + row * SROW + half * 4) * 4u;
        size_t go = (size_t)row * K + (size_t)kt * 16 + half * 8;
        cp16(db + 0u * STGU * 4u, Ah + (size_t)bm * K + go);
        cp16(db + 1u * STGU * 4u / 1u * 0u + 1u * PLU * 4u, Al + (size_t)bm * K + go);
        cp16(db + 2u * PLU * 4u, Bh + (size_t)bn * K + go);
        cp16(db + 3u * PLU * 4u, Bl + (size_t)bn * K + go);
    };

    float acc[4][4][4] = {};

    auto compute = [&](int slot) {
        const uint32_t* S = smu + slot * STGU;
        const uint32_t* pAh = S;
        const uint32_t* pAl = S + PLU;
        const uint32_t* pBh = S + 2 * PLU;
        const uint32_t* pBl = S + 3 * PLU;
        uint32_t bh[4][2], bl[4][2];
        #pragma unroll
        for (int nt = 0; nt < 4; nt++) {
            int o = (wn + nt * 8 + r) * SROW + cf;
            bh[nt][0] = pBh[o]; bh[nt][1] = pBh[o + 4];
            bl[nt][0] = pBl[o]; bl[nt][1] = pBl[o + 4];
        }
        #pragma unroll
        for (int mt = 0; mt < 4; mt++) {
            int o = (wm + mt * 16 + r) * SROW + cf;
            uint32_t ah[4], al[4];
            ah[0] = pAh[o];            ah[1] = pAh[o + 8 * SROW];
            ah[2] = pAh[o + 4];        ah[3] = pAh[o + 8 * SROW + 4];
            al[0] = pAl[o];            al[1] = pAl[o + 8 * SROW];
            al[2] = pAl[o + 4];        al[3] = pAl[o + 8 * SROW + 4];
            #pragma unroll
            for (int nt = 0; nt < 4; nt++) {
                mma_bf16(acc[mt][nt], ah, bh[nt]);
                mma_bf16(acc[mt][nt], ah, bl[nt]);
                mma_bf16(acc[mt][nt], al, bh[nt]);
            }
        }
    };

    const int NK = K / 16;
    copy(0, 0); CP_COMMIT();
    copy(1, 1); CP_COMMIT();
    copy(2, 2); CP_COMMIT();
    for (int kt = 0; kt < NK; kt++) {
        CP_WAIT2();                       // stage kt arrived (3 commits back)
        __syncthreads();
        if (kt + 3 < NK) copy(kt + 3, (kt + 3) & 3);
        CP_COMMIT();                      // uniform commit (possibly empty)
        compute(kt & 3);
    }

    // Epilogue: mma C-fragment layout, float2 stores
    #pragma unroll
    for (int mt = 0; mt < 4; mt++) {
        int rowc = bm + wm + mt * 16 + r;
        #pragma unroll
        for (int nt = 0; nt < 4; nt++) {
            int col = bn + wn + nt * 8 + cf * 2;
            float2 lo = {acc[mt][nt][0], acc[mt][nt][1]};
            float2 hi = {acc[mt][nt][2], acc[mt][nt][3]};
            *(float2*)(C + (size_t)rowc * Ncol + col) = lo;
            *(float2*)(C + (size_t)(rowc + 8) * Ncol + col) = hi;
        }
    }
}

// K/V/Q projections fused via blockIdx.z
__global__ void __launch_bounds__(256, 2) gemm_kvq() {
    const bf16 *Bh, *Bl;
    float* C;
    if (blockIdx.z == 0)      { Bh = d_wKh; Bl = d_wKl; C = d_K; }
    else if (blockIdx.z == 1) { Bh = d_wVh; Bl = d_wVl; C = d_V; }
    else                      { Bh = d_wQh; Bl = d_wQl; C = d_Q; }
    gemm3_tile(d_Xh + (size_t)blockIdx.y * 128 * 1024, d_Xl + (size_t)blockIdx.y * 128 * 1024,
               Bh + (size_t)blockIdx.x * 128 * 1024, Bl + (size_t)blockIdx.x * 128 * 1024,
               C + (size_t)blockIdx.y * 128 * 512 + blockIdx.x * 128,
               512, 1024, 0, 0);
}

// Output GEMM: out = Y * wO = Y * (wOT)^T
__global__ void __launch_bounds__(256, 2) gemm_out(float* __restrict__ out) {
    gemm3_tile(d_Yh + (size_t)blockIdx.y * 128 * 512, d_Yl + (size_t)blockIdx.y * 128 * 512,
               d_wOh + (size_t)blockIdx.x * 128 * 512, d_wOl + (size_t)blockIdx.x * 128 * 512,
               out + (size_t)blockIdx.y * 128 * 1024 + blockIdx.x * 128,
               1024, 512, 0, 0);
}

// ---------------------------------------------------------------------------
// One-shot weight split: wK/wV/wQ -> bf16 hi/lo planes (by blockIdx.y)
// ---------------------------------------------------------------------------
__global__ void __launch_bounds__(256) split_w(const float* __restrict__ wK,
                                               const float* __restrict__ wV,
                                               const float* __restrict__ wQ) {
    const float* src = (blockIdx.y == 0) ? wK : (blockIdx.y == 1) ? wV : wQ;
    bf16* dh = (blockIdx.y == 0) ? d_wKh : (blockIdx.y == 1) ? d_wVh : d_wQh;
    bf16* dl = (blockIdx.y == 0) ? d_wKl : (blockIdx.y == 1) ? d_wVl : d_wQl;
    int i = blockIdx.x * 256 + threadIdx.x;      // float4 index, 131072 total
    float4 v = *(const float4*)(src + (size_t)i * 4);
    bf16 h[4], l[4];
    split_bf(v.x, h[0], l[0]); split_bf(v.y, h[1], l[1]);
    split_bf(v.z, h[2], l[2]); split_bf(v.w, h[3], l[3]);
    *(bf162*)(dh + (size_t)i * 4)     = bf162{h[0], h[1]};
    *(bf162*)(dh + (size_t)i * 4 + 2) = bf162{h[2], h[3]};
    *(bf162*)(dl + (size_t)i * 4)     = bf162{l[0], l[1]};
    *(bf162*)(dl + (size_t)i * 4 + 2) = bf162{l[2], l[3]};
}

// wO (512 x 1024 row-major) -> transposed + split (1024 x 512) bf16 hi/lo
__global__ void transpose_wo(const float* __restrict__ wo) {
    __shared__ float t[32][33];
    int bx = blockIdx.x * 32;   // over N (1024)
    int by = blockIdx.y * 32;   // over K (512)
    int x = threadIdx.x, y = threadIdx.y;
    #pragma unroll
    for (int j = 0; j < 32; j += 8)
        t[y + j][x] = wo[(size_t)(by + y + j) * 1024 + bx + x];
    __syncthreads();
    #pragma unroll
    for (int j = 0; j < 32; j += 8) {
        float v = t[x][y + j];
        bf16 h, l;
        split_bf(v, h, l);
        d_wOh[(size_t)(bx + y + j) * 512 + by + x] = h;
        d_wOl[(size_t)(bx + y + j) * 512 + by + x] = l;
    }
}

// ---------------------------------------------------------------------------
// G projection + bias + sigmoid; also emits X hi/lo bf16 planes.
// ---------------------------------------------------------------------------
__global__ void __launch_bounds__(256) g_kernel(const float* __restrict__ X,
                                                const float* __restrict__ wG,
                                                const float* __restrict__ bG) {
    __shared__ float xs[8][1024];
    const int tid = threadIdx.x;
    const int token0 = blockIdx.x * 8;
    #pragma unroll
    for (int i = 0; i < 8; i++) {
        int idx = tid + i * 256;              // float4 index 0..2047
        int tok = idx >> 8, c4 = idx & 255;
        float4 v = *(const float4*)(X + (size_t)(token0 + tok) * DMc + c4 * 4);
        *(float4*)&xs[tok][c4 * 4] = v;
        bf16 h[4], l[4];
        split_bf(v.x, h[0], l[0]); split_bf(v.y, h[1], l[1]);
        split_bf(v.z, h[2], l[2]); split_bf(v.w, h[3], l[3]);
        size_t o = (size_t)(token0 + tok) * DMc + c4 * 4;
        *(bf162*)(d_Xh + o)     = bf162{h[0], h[1]};
        *(bf162*)(d_Xh + o + 2) = bf162{h[2], h[3]};
        *(bf162*)(d_Xl + o)     = bf162{l[0], l[1]};
        *(bf162*)(d_Xl + o + 2) = bf162{l[2], l[3]};
    }
    __syncthreads();

    const int w = tid >> 5, lane = tid & 31;
    float acc[4][8] = {};
    #pragma unroll 4
    for (int j = 0; j < 32; j++) {
        int k = j * 32 + lane;
        float wv[4];
        #pragma unroll
        for (int o = 0; o < 4; o++)
            wv[o] = wG[(size_t)(w * 4 + o) * DMc + k];
        #pragma unroll
        for (int tok = 0; tok < 8; tok++) {
            float xv = xs[tok][k];
            #pragma unroll
            for (int o = 0; o < 4; o++)
                acc[o][tok] += wv[o] * xv;
        }
    }
    #pragma unroll
    for (int o = 0; o < 4; o++) {
        float bias = bG[w * 4 + o];
        #pragma unroll
        for (int tok = 0; tok < 8; tok++) {
            float v = acc[o][tok];
            #pragma unroll
            for (int off = 16; off; off >>= 1)
                v += __shfl_xor_sync(0xffffffffu, v, off);
            if (lane == 0)
                d_Gsig[(size_t)(token0 + tok) * (Hh * Ee) + w * 4 + o] =
                    1.f / (1.f + expf(-(v + bias)));
        }
    }
}

// ---------------------------------------------------------------------------
// Gating: per (n,e,t) compute gated_K, gated_V (sum over heads), and A.
// ---------------------------------------------------------------------------
__global__ void __launch_bounds__(128) gated_kernel() {
    const int blk = blockIdx.x;
    const int t = blk % Tt;
    const int e = (blk / Tt) % Ee;
    const int n = blk / (Tt * Ee);
    const int token = n * Tt + t;
    __shared__ float g[Hh];
    const int tid = threadIdx.x;
    if (tid < Hh)
        g[tid] = d_Gsig[token * (Hh * Ee) + tid * Ee + e];
    __syncthreads();
    if (tid < 64) {
        float s = 0.f;
        #pragma unroll
        for (int h = 0; h < Hh; h++) s += g[h] * d_K[token * (Hh * DKc) + h * DKc + tid];
        d_gK[((n * Ee + e) * Tt + t) * DKc + tid] = s;
    } else {
        int dd = tid - 64;
        float s = 0.f;
        #pragma unroll
        for (int h = 0; h < Hh; h++) s += g[h] * d_V[token * (Hh * DVc) + h * DVc + dd];
        d_gV[((n * Ee + e) * Tt + t) * DVc + dd] = s;
    }
    if (tid == 0) {
        float sa = 0.f;
        #pragma unroll
        for (int h = 0; h < Hh; h++) sa += g[h];
        d_A[(n * Ee + e) * Tt + t] = 1.f - sa;
    }
}

// ---------------------------------------------------------------------------
// Scan: L-strided recurrence rec[t] = A[t]*rec[t-L] + gated[t].
// ---------------------------------------------------------------------------
__global__ void __launch_bounds__(128) scan_kernel(const float* __restrict__ initK,
                                                   const float* __restrict__ initV) {
    const int b = blockIdx.x;             // Nn*Ee*Ll = 256 blocks
    const int l = b % Ll;
    const int e = (b / Ll) % Ee;
    const int n = b / (Ll * Ee);
    const int d = threadIdx.x;
    const bool isK = d < 64;
    const int dd = isK ? d : d - 64;
    const float* init = isK ? initK : initV;
    const float* gsrc = isK ? d_gK : d_gV;
    float* rec = isK ? d_recK : d_recV;
    const int ne = n * Ee + e;
    float y = init[(e * Ll + l) * 64 + dd];
    rec[(ne * REC_T + l) * 64 + dd] = y;
    const float* Arow = d_A + ne * Tt;
    const float* grow = gsrc + ne * Tt * 64;
    float* rrow = rec + (ne * REC_T + Ll) * 64;
    #pragma unroll 4
    for (int m = 0; m < M_CH; m++) {
        int t = m * Ll + l;
        y = Arow[t] * y + grow[t * 64 + dd];
        rrow[t * 64 + dd] = y;
    }
}

// ---------------------------------------------------------------------------
// Attention: one block per token (n,t); all H=8 heads share the same
// 128-slot key/value window (E=4 experts x L=32 positions).
// Epilogue writes Y directly as bf16 hi/lo planes for the output GEMM.
// ---------------------------------------------------------------------------
__global__ void __launch_bounds__(256) attn_kernel() {
    extern __shared__ float smem[];
    float* qs = smem;                      // 512
    float* Ks = qs + Hh * DKc;             // 128*65 (padded rows)
    float* Vs = Ks + 128 * 65;             // 128*65
    float* sc = Vs + 128 * 65;             // 8*128
    const int token = blockIdx.x;
    const int n = token / Tt, t = token % Tt;
    const int tid = threadIdx.x;

    qs[tid]       = d_Q[token * 512 + tid];
    qs[tid + 256] = d_Q[token * 512 + tid + 256];

    for (int i = tid; i < 128 * 64; i += 256) {
        int j = i >> 6, dd = i & 63;
        int e = j >> 5;
        int pos = t + (j & 31) + 1;                 // <= 2079 < REC_T
        int off = ((n * Ee + e) * REC_T + pos) * 64 + dd;
        Ks[j * 65 + dd] = d_recK[off];
        Vs[j * 65 + dd] = d_recV[off];
    }
    __syncthreads();

    // scores: 8 heads x 128 slots = 1024 tasks
    #pragma unroll
    for (int r = 0; r < 4; r++) {
        int task = tid + r * 256;
        int h = task >> 7, j = task & 127;
        const float* qrow = qs + h * 64;
        const float* krow = Ks + j * 65;
        float s = 0.f;
        #pragma unroll
        for (int d = 0; d < 64; d++) s += qrow[d] * krow[d];
        sc[h * 128 + j] = s * 0.125f;               // 1/sqrt(64)
    }
    __syncthreads();

    // softmax over 128 slots: warp w handles head h=w
    {
        int h = tid >> 5, lane = tid & 31;
        float v0 = sc[h * 128 + lane];
        float v1 = sc[h * 128 + lane + 32];
        float v2 = sc[h * 128 + lane + 64];
        float v3 = sc[h * 128 + lane + 96];
        float mx = fmaxf(fmaxf(v0, v1), fmaxf(v2, v3));
        #pragma unroll
        for (int o = 16; o; o >>= 1) mx = fmaxf(mx, __shfl_xor_sync(0xffffffffu, mx, o));
        float e0 = expf(v0 - mx), e1 = expf(v1 - mx);
        float e2 = expf(v2 - mx), e3 = expf(v3 - mx);
        float ssum = e0 + e1 + e2 + e3;
        #pragma unroll
        for (int o = 16; o; o >>= 1) ssum += __shfl_xor_sync(0xffffffffu, ssum, o);
        float inv = 1.f / ssum;
        sc[h * 128 + lane]      = e0 * inv;
        sc[h * 128 + lane + 32] = e1 * inv;
        sc[h * 128 + lane + 64] = e2 * inv;
        sc[h * 128 + lane + 96] = e3 * inv;
    }
    __syncthreads();

    // output: 8 heads x 64 dims = 512 outputs, split to bf16 hi/lo
    #pragma unroll
    for (int r = 0; r < 2; r++) {
        int o = tid + r * 256;
        int h = o >> 6, dd = o & 63;
        const float* arow = sc + h * 128;
        float acc = 0.f;
        #pragma unroll 4
        for (int j = 0; j < 128; j++) acc += arow[j] * Vs[j * 65 + dd];
        bf16 hp, lp;
        split_bf(acc, hp, lp);
        d_Yh[token * 512 + o] = hp;
        d_Yl[token * 512 + o] = lp;
    }
}

// ---------------------------------------------------------------------------
extern "C" void kernel_launch(void* const* d_in, const int* in_sizes, int n_in,
                              void* d_out, int out_size) {
    const float* X  = (const float*)d_in[0];
    const float* wG = (const float*)d_in[1];
    const float* bG = (const float*)d_in[2];
    const float* wK = (const float*)d_in[3];
    const float* wV = (const float*)d_in[4];
    const float* wQ = (const float*)d_in[5];
    const float* wO = (const float*)d_in[6];
    const float* iK = (const float*)d_in[7];
    const float* iV = (const float*)d_in[8];
    float* out = (float*)d_out;

    cudaFuncSetAttribute(gemm_kvq, cudaFuncAttributeMaxDynamicSharedMemorySize, GSMB);
    cudaFuncSetAttribute(gemm_out, cudaFuncAttributeMaxDynamicSharedMemorySize, GSMB);

    // One-shot operand preparation (splits + transpose)
    split_w<<<dim3(512, 3), 256>>>(wK, wV, wQ);
    transpose_wo<<<dim3(32, 16), dim3(32, 8)>>>(wO);
    g_kernel<<<NT / 8, 256>>>(X, wG, bG);     // also emits d_Xh / d_Xl

    // K/V/Q projections on pre-split bf16 planes, fused on grid.z
    gemm_kvq<<<dim3(4, 32, 3), 256, GSMB>>>();

    gated_kernel<<<Nn * Ee * Tt, 128>>>();
    scan_kernel<<<Nn * Ee * Ll, 128>>>(iK, iV);

    static const size_t attn_smem = (512 + 2 * 128 * 65 + 8 * 128) * sizeof(float);
    cudaFuncSetAttribute(attn_kernel, cudaFuncAttributeMaxDynamicSharedMemorySize,
                         (int)attn_smem);
    attn_kernel<<<NT, 256, attn_smem>>>();

    // Output: out = Y * wO = Y * (wOT)^T
    gemm_out<<<dim3(8, 32), 256, GSMB>>>(out);
}

// round 10
// speedup vs baseline: 4.7450x; 1.0789x over previous
#include <cuda_runtime.h>
#include <cuda_bf16.h>
#include <math.h>
#include <stdint.h>

// Problem constants
#define Nn 2
#define Tt 2048
#define DMc 1024
#define Hh 8
#define Ee 4
#define Ll 32
#define DKc 64
#define DVc 64
#define NT (Nn*Tt)           // 4096 tokens
#define REC_T (Tt+Ll)        // 2080 rec positions per (n,e)
#define M_CH (Tt/Ll)         // 64 chunks

typedef __nv_bfloat16 bf16;
typedef __nv_bfloat162 bf162;

// Scratch (allocation-free rule: __device__ globals)
__device__ float d_K[NT*Hh*DKc];       // (token, h*64+d)
__device__ float d_V[NT*Hh*DVc];
__device__ float d_Q[NT*Hh*DKc];
__device__ float d_Gsig[NT*Hh*Ee];     // (token, h*4+e) POST-sigmoid
__device__ float d_A[Nn*Ee*Tt];        // (n,e,t)
__device__ float d_gK[Nn*Ee*Tt*DKc];   // (n,e,t,d)
__device__ float d_gV[Nn*Ee*Tt*DVc];
__device__ float d_recK[Nn*Ee*REC_T*DKc]; // (n,e,pos,d), pos 0..L-1 = init
__device__ float d_recV[Nn*Ee*REC_T*DVc];

// Pre-split bf16 hi/lo planes
__device__ bf16 d_Xh[NT*DMc],    d_Xl[NT*DMc];
__device__ bf16 d_wKh[512*1024], d_wKl[512*1024];
__device__ bf16 d_wVh[512*1024], d_wVl[512*1024];
__device__ bf16 d_wQh[512*1024], d_wQl[512*1024];
__device__ bf16 d_wOh[1024*512], d_wOl[1024*512];   // wO transposed + split
__device__ bf16 d_Yh[NT*Hh*DVc], d_Yl[NT*Hh*DVc];

// ---------------------------------------------------------------------------
// helpers
// ---------------------------------------------------------------------------
__device__ __forceinline__ uint32_t smem_u32(const void* p) {
    uint32_t a;
    asm("{ .reg .u64 t; cvta.to.shared.u64 t, %1; cvt.u32.u64 %0, t; }"
        : "=r"(a) : "l"(p));
    return a;
}

__device__ __forceinline__ void split_bf(float x, bf16& h, bf16& l) {
    h = __float2bfloat16(x);
    l = __float2bfloat16(x - __bfloat162float(h));
}

__device__ __forceinline__ void mma_bf16(float* c, const uint32_t* a, const uint32_t* b) {
    asm volatile("mma.sync.aligned.m16n8k16.row.col.f32.bf16.bf16.f32 "
        "{%0,%1,%2,%3}, {%4,%5,%6,%7}, {%8,%9}, {%0,%1,%2,%3};"
        : "+f"(c[0]), "+f"(c[1]), "+f"(c[2]), "+f"(c[3])
        : "r"(a[0]), "r"(a[1]), "r"(a[2]), "r"(a[3]), "r"(b[0]), "r"(b[1]));
}

__device__ __forceinline__ void ldsm4(uint32_t* r, uint32_t addr) {
    asm volatile("ldmatrix.sync.aligned.m8n8.x4.shared.b16 {%0,%1,%2,%3}, [%4];"
        : "=r"(r[0]), "=r"(r[1]), "=r"(r[2]), "=r"(r[3]) : "r"(addr));
}

__device__ __forceinline__ void cp16(uint32_t dst, const void* src) {
    asm volatile("cp.async.cg.shared.global [%0], [%1], 16;" :: "r"(dst), "l"(src));
}
#define CP_COMMIT() asm volatile("cp.async.commit_group;" ::: "memory")
#define CP_WAIT2()  asm volatile("cp.async.wait_group 2;" ::: "memory")

// ---------------------------------------------------------------------------
// 3x-split bf16 GEMM (m16n8k16 + ldmatrix): C[128x128] tile.
//  A planes: [Mtot, K] bf16 row-major; B planes: [Ntot, K] bf16 row-major
//  (C = A * B^T, fp32 accumulate; acc = AhBh + AhBl + AlBh).
// 256 threads, warp tile 64x32. smem: 4-stage ring; per stage 4 planes of
// 128 rows x 12 uint32 (8 data kpairs + 4 pad -> LDSM-phase conflict-free).
// ---------------------------------------------------------------------------
#define SROW 12                        // uint32 per row
#define PLU (128*SROW)                 // uint32 per plane = 1536
#define STGU (4*PLU)                   // uint32 per stage = 6144 (24KB)
#define GSMB (4*STGU*4)                // bytes = 98304 (4 stages)

__device__ __forceinline__ void gemm3_tile(const bf16* __restrict__ Ah,
                                           const bf16* __restrict__ Al,
                                           const bf16* __restrict__ Bh,
                                           const bf16* __restrict__ Bl,
                                           float* __restrict__ C,
                                           int Ncol, int K) {
    extern __shared__ uint32_t smu[];
    const uint32_t sbase = smem_u32(smu);
    const int tid = threadIdx.x;
    const int warp = tid >> 5, lane = tid & 31;
    const int wm = (warp >> 2) * 64;      // 0 / 64
    const int wn = (warp & 3) * 32;       // 0..96
    const int r = lane >> 2, cf = lane & 3;

    const int row = tid >> 1, half = tid & 1;   // loader: 1 seg/plane/thread

    auto copy = [&](int kt, int slot) {
        uint32_t db = sbase + (uint32_t)(slot * STGU + row * SROW + half * 4) * 4u;
        size_t go = (size_t)row * K + (size_t)kt * 16 + half * 8;
        cp16(db,                Ah + go);
        cp16(db + PLU * 4u,     Al + go);
        cp16(db + 2u * PLU * 4u, Bh + go);
        cp16(db + 3u * PLU * 4u, Bl + go);
    };

    // ldmatrix lane-address components
    const uint32_t a_row = (uint32_t)(wm + ((lane >> 3) & 1) * 8 + (lane & 7));
    const uint32_t a_kof = (uint32_t)((lane >> 4) * 4);
    const uint32_t b_row = (uint32_t)(wn + ((lane >> 4) & 1) * 8 + (lane & 7));
    const uint32_t b_kof = (uint32_t)(((lane >> 3) & 1) * 4);

    float acc[4][4][4] = {};

    auto compute = [&](int slot) {
        const uint32_t S = sbase + (uint32_t)(slot * STGU) * 4u;
        uint32_t bh[2][4], bl[2][4];      // [nt-pair][4 regs]
        #pragma unroll
        for (int p = 0; p < 2; p++) {
            uint32_t ad = S + 2u * PLU * 4u + ((b_row + p * 16) * SROW + b_kof) * 4u;
            ldsm4(bh[p], ad);
            ldsm4(bl[p], ad + PLU * 4u);
        }
        #pragma unroll
        for (int mt = 0; mt < 4; mt++) {
            uint32_t ah[4], al[4];
            uint32_t ad = S + ((a_row + mt * 16) * SROW + a_kof) * 4u;
            ldsm4(ah, ad);
            ldsm4(al, ad + PLU * 4u);
            #pragma unroll
            for (int nt = 0; nt < 4; nt++) {
                const uint32_t* bhp = &bh[nt >> 1][(nt & 1) * 2];
                const uint32_t* blp = &bl[nt >> 1][(nt & 1) * 2];
                mma_bf16(acc[mt][nt], ah, bhp);
                mma_bf16(acc[mt][nt], ah, blp);
                mma_bf16(acc[mt][nt], al, bhp);
            }
        }
    };

    const int NK = K / 16;
    copy(0, 0); CP_COMMIT();
    copy(1, 1); CP_COMMIT();
    copy(2, 2); CP_COMMIT();
    for (int kt = 0; kt < NK; kt++) {
        CP_WAIT2();                       // stage kt arrived (3 commits back)
        __syncthreads();
        if (kt + 3 < NK) copy(kt + 3, (kt + 3) & 3);
        CP_COMMIT();                      // uniform commit (possibly empty)
        compute(kt & 3);
    }

    // Epilogue: mma C-fragment layout, float2 stores
    #pragma unroll
    for (int mt = 0; mt < 4; mt++) {
        int rowc = wm + mt * 16 + r;
        #pragma unroll
        for (int nt = 0; nt < 4; nt++) {
            int col = wn + nt * 8 + cf * 2;
            float2 lo = {acc[mt][nt][0], acc[mt][nt][1]};
            float2 hi = {acc[mt][nt][2], acc[mt][nt][3]};
            *(float2*)(C + (size_t)rowc * Ncol + col) = lo;
            *(float2*)(C + (size_t)(rowc + 8) * Ncol + col) = hi;
        }
    }
}

// K/V/Q projections fused via blockIdx.z
__global__ void __launch_bounds__(256, 2) gemm_kvq() {
    const bf16 *Bh, *Bl;
    float* C;
    if (blockIdx.z == 0)      { Bh = d_wKh; Bl = d_wKl; C = d_K; }
    else if (blockIdx.z == 1) { Bh = d_wVh; Bl = d_wVl; C = d_V; }
    else                      { Bh = d_wQh; Bl = d_wQl; C = d_Q; }
    gemm3_tile(d_Xh + (size_t)blockIdx.y * 128 * 1024, d_Xl + (size_t)blockIdx.y * 128 * 1024,
               Bh + (size_t)blockIdx.x * 128 * 1024, Bl + (size_t)blockIdx.x * 128 * 1024,
               C + (size_t)blockIdx.y * 128 * 512 + blockIdx.x * 128,
               512, 1024);
}

// Output GEMM: out = Y * wO = Y * (wOT)^T
__global__ void __launch_bounds__(256, 2) gemm_out(float* __restrict__ out) {
    gemm3_tile(d_Yh + (size_t)blockIdx.y * 128 * 512, d_Yl + (size_t)blockIdx.y * 128 * 512,
               d_wOh + (size_t)blockIdx.x * 128 * 512, d_wOl + (size_t)blockIdx.x * 128 * 512,
               out + (size_t)blockIdx.y * 128 * 1024 + blockIdx.x * 128,
               1024, 512);
}

// ---------------------------------------------------------------------------
// One-shot weight split: wK/wV/wQ -> bf16 hi/lo planes (by blockIdx.y)
// ---------------------------------------------------------------------------
__global__ void __launch_bounds__(256) split_w(const float* __restrict__ wK,
                                               const float* __restrict__ wV,
                                               const float* __restrict__ wQ) {
    const float* src = (blockIdx.y == 0) ? wK : (blockIdx.y == 1) ? wV : wQ;
    bf16* dh = (blockIdx.y == 0) ? d_wKh : (blockIdx.y == 1) ? d_wVh : d_wQh;
    bf16* dl = (blockIdx.y == 0) ? d_wKl : (blockIdx.y == 1) ? d_wVl : d_wQl;
    int i = blockIdx.x * 256 + threadIdx.x;      // float4 index, 131072 total
    float4 v = *(const float4*)(src + (size_t)i * 4);
    bf16 h[4], l[4];
    split_bf(v.x, h[0], l[0]); split_bf(v.y, h[1], l[1]);
    split_bf(v.z, h[2], l[2]); split_bf(v.w, h[3], l[3]);
    *(bf162*)(dh + (size_t)i * 4)     = bf162{h[0], h[1]};
    *(bf162*)(dh + (size_t)i * 4 + 2) = bf162{h[2], h[3]};
    *(bf162*)(dl + (size_t)i * 4)     = bf162{l[0], l[1]};
    *(bf162*)(dl + (size_t)i * 4 + 2) = bf162{l[2], l[3]};
}

// wO (512 x 1024 row-major) -> transposed + split (1024 x 512) bf16 hi/lo
__global__ void transpose_wo(const float* __restrict__ wo) {
    __shared__ float t[32][33];
    int bx = blockIdx.x * 32;   // over N (1024)
    int by = blockIdx.y * 32;   // over K (512)
    int x = threadIdx.x, y = threadIdx.y;
    #pragma unroll
    for (int j = 0; j < 32; j += 8)
        t[y + j][x] = wo[(size_t)(by + y + j) * 1024 + bx + x];
    __syncthreads();
    #pragma unroll
    for (int j = 0; j < 32; j += 8) {
        float v = t[x][y + j];
        bf16 h, l;
        split_bf(v, h, l);
        d_wOh[(size_t)(bx + y + j) * 512 + by + x] = h;
        d_wOl[(size_t)(bx + y + j) * 512 + by + x] = l;
    }
}

// ---------------------------------------------------------------------------
// G projection + bias + sigmoid; also emits X hi/lo bf16 planes.
// ---------------------------------------------------------------------------
__global__ void __launch_bounds__(256) g_kernel(const float* __restrict__ X,
                                                const float* __restrict__ wG,
                                                const float* __restrict__ bG) {
    __shared__ float xs[8][1024];
    const int tid = threadIdx.x;
    const int token0 = blockIdx.x * 8;
    #pragma unroll
    for (int i = 0; i < 8; i++) {
        int idx = tid + i * 256;              // float4 index 0..2047
        int tok = idx >> 8, c4 = idx & 255;
        float4 v = *(const float4*)(X + (size_t)(token0 + tok) * DMc + c4 * 4);
        *(float4*)&xs[tok][c4 * 4] = v;
        bf16 h[4], l[4];
        split_bf(v.x, h[0], l[0]); split_bf(v.y, h[1], l[1]);
        split_bf(v.z, h[2], l[2]); split_bf(v.w, h[3], l[3]);
        size_t o = (size_t)(token0 + tok) * DMc + c4 * 4;
        *(bf162*)(d_Xh + o)     = bf162{h[0], h[1]};
        *(bf162*)(d_Xh + o + 2) = bf162{h[2], h[3]};
        *(bf162*)(d_Xl + o)     = bf162{l[0], l[1]};
        *(bf162*)(d_Xl + o + 2) = bf162{l[2], l[3]};
    }
    __syncthreads();

    const int w = tid >> 5, lane = tid & 31;
    float acc[4][8] = {};
    #pragma unroll 4
    for (int j = 0; j < 32; j++) {
        int k = j * 32 + lane;
        float wv[4];
        #pragma unroll
        for (int o = 0; o < 4; o++)
            wv[o] = wG[(size_t)(w * 4 + o) * DMc + k];
        #pragma unroll
        for (int tok = 0; tok < 8; tok++) {
            float xv = xs[tok][k];
            #pragma unroll
            for (int o = 0; o < 4; o++)
                acc[o][tok] += wv[o] * xv;
        }
    }
    #pragma unroll
    for (int o = 0; o < 4; o++) {
        float bias = bG[w * 4 + o];
        #pragma unroll
        for (int tok = 0; tok < 8; tok++) {
            float v = acc[o][tok];
            #pragma unroll
            for (int off = 16; off; off >>= 1)
                v += __shfl_xor_sync(0xffffffffu, v, off);
            if (lane == 0)
                d_Gsig[(size_t)(token0 + tok) * (Hh * Ee) + w * 4 + o] =
                    1.f / (1.f + expf(-(v + bias)));
        }
    }
}

// ---------------------------------------------------------------------------
// Gating: per (n,e,t) compute gated_K, gated_V (sum over heads), and A.
// ---------------------------------------------------------------------------
__global__ void __launch_bounds__(128) gated_kernel() {
    const int blk = blockIdx.x;
    const int t = blk % Tt;
    const int e = (blk / Tt) % Ee;
    const int n = blk / (Tt * Ee);
    const int token = n * Tt + t;
    __shared__ float g[Hh];
    const int tid = threadIdx.x;
    if (tid < Hh)
        g[tid] = d_Gsig[token * (Hh * Ee) + tid * Ee + e];
    __syncthreads();
    if (tid < 64) {
        float s = 0.f;
        #pragma unroll
        for (int h = 0; h < Hh; h++) s += g[h] * d_K[token * (Hh * DKc) + h * DKc + tid];
        d_gK[((n * Ee + e) * Tt + t) * DKc + tid] = s;
    } else {
        int dd = tid - 64;
        float s = 0.f;
        #pragma unroll
        for (int h = 0; h < Hh; h++) s += g[h] * d_V[token * (Hh * DVc) + h * DVc + dd];
        d_gV[((n * Ee + e) * Tt + t) * DVc + dd] = s;
    }
    if (tid == 0) {
        float sa = 0.f;
        #pragma unroll
        for (int h = 0; h < Hh; h++) sa += g[h];
        d_A[(n * Ee + e) * Tt + t] = 1.f - sa;
    }
}

// ---------------------------------------------------------------------------
// Scan: L-strided recurrence rec[t] = A[t]*rec[t-L] + gated[t].
// ---------------------------------------------------------------------------
__global__ void __launch_bounds__(128) scan_kernel(const float* __restrict__ initK,
                                                   const float* __restrict__ initV) {
    const int b = blockIdx.x;             // Nn*Ee*Ll = 256 blocks
    const int l = b % Ll;
    const int e = (b / Ll) % Ee;
    const int n = b / (Ll * Ee);
    const int d = threadIdx.x;
    const bool isK = d < 64;
    const int dd = isK ? d : d - 64;
    const float* init = isK ? initK : initV;
    const float* gsrc = isK ? d_gK : d_gV;
    float* rec = isK ? d_recK : d_recV;
    const int ne = n * Ee + e;
    float y = init[(e * Ll + l) * 64 + dd];
    rec[(ne * REC_T + l) * 64 + dd] = y;
    const float* Arow = d_A + ne * Tt;
    const float* grow = gsrc + ne * Tt * 64;
    float* rrow = rec + (ne * REC_T + Ll) * 64;
    #pragma unroll 4
    for (int m = 0; m < M_CH; m++) {
        int t = m * Ll + l;
        y = Arow[t] * y + grow[t * 64 + dd];
        rrow[t * 64 + dd] = y;
    }
}

// ---------------------------------------------------------------------------
// Attention: one block per token (n,t); all H=8 heads share the same
// 128-slot key/value window (E=4 experts x L=32 positions).
// Epilogue writes Y directly as bf16 hi/lo planes for the output GEMM.
// ---------------------------------------------------------------------------
__global__ void __launch_bounds__(256) attn_kernel() {
    extern __shared__ float smem[];
    float* qs = smem;                      // 512
    float* Ks = qs + Hh * DKc;             // 128*65 (padded rows)
    float* Vs = Ks + 128 * 65;             // 128*65
    float* sc = Vs + 128 * 65;             // 8*128
    const int token = blockIdx.x;
    const int n = token / Tt, t = token % Tt;
    const int tid = threadIdx.x;

    qs[tid]       = d_Q[token * 512 + tid];
    qs[tid + 256] = d_Q[token * 512 + tid + 256];

    for (int i = tid; i < 128 * 64; i += 256) {
        int j = i >> 6, dd = i & 63;
        int e = j >> 5;
        int pos = t + (j & 31) + 1;                 // <= 2079 < REC_T
        int off = ((n * Ee + e) * REC_T + pos) * 64 + dd;
        Ks[j * 65 + dd] = d_recK[off];
        Vs[j * 65 + dd] = d_recV[off];
    }
    __syncthreads();

    // scores: 8 heads x 128 slots = 1024 tasks
    #pragma unroll
    for (int r = 0; r < 4; r++) {
        int task = tid + r * 256;
        int h = task >> 7, j = task & 127;
        const float* qrow = qs + h * 64;
        const float* krow = Ks + j * 65;
        float s = 0.f;
        #pragma unroll
        for (int d = 0; d < 64; d++) s += qrow[d] * krow[d];
        sc[h * 128 + j] = s * 0.125f;               // 1/sqrt(64)
    }
    __syncthreads();

    // softmax over 128 slots: warp w handles head h=w
    {
        int h = tid >> 5, lane = tid & 31;
        float v0 = sc[h * 128 + lane];
        float v1 = sc[h * 128 + lane + 32];
        float v2 = sc[h * 128 + lane + 64];
        float v3 = sc[h * 128 + lane + 96];
        float mx = fmaxf(fmaxf(v0, v1), fmaxf(v2, v3));
        #pragma unroll
        for (int o = 16; o; o >>= 1) mx = fmaxf(mx, __shfl_xor_sync(0xffffffffu, mx, o));
        float e0 = expf(v0 - mx), e1 = expf(v1 - mx);
        float e2 = expf(v2 - mx), e3 = expf(v3 - mx);
        float ssum = e0 + e1 + e2 + e3;
        #pragma unroll
        for (int o = 16; o; o >>= 1) ssum += __shfl_xor_sync(0xffffffffu, ssum, o);
        float inv = 1.f / ssum;
        sc[h * 128 + lane]      = e0 * inv;
        sc[h * 128 + lane + 32] = e1 * inv;
        sc[h * 128 + lane + 64] = e2 * inv;
        sc[h * 128 + lane + 96] = e3 * inv;
    }
    __syncthreads();

    // output: 8 heads x 64 dims = 512 outputs, split to bf16 hi/lo
    #pragma unroll
    for (int r = 0; r < 2; r++) {
        int o = tid + r * 256;
        int h = o >> 6, dd = o & 63;
        const float* arow = sc + h * 128;
        float acc = 0.f;
        #pragma unroll 4
        for (int j = 0; j < 128; j++) acc += arow[j] * Vs[j * 65 + dd];
        bf16 hp, lp;
        split_bf(acc, hp, lp);
        d_Yh[token * 512 + o] = hp;
        d_Yl[token * 512 + o] = lp;
    }
}

// ---------------------------------------------------------------------------
extern "C" void kernel_launch(void* const* d_in, const int* in_sizes, int n_in,
                              void* d_out, int out_size) {
    const float* X  = (const float*)d_in[0];
    const float* wG = (const float*)d_in[1];
    const float* bG = (const float*)d_in[2];
    const float* wK = (const float*)d_in[3];
    const float* wV = (const float*)d_in[4];
    const float* wQ = (const float*)d_in[5];
    const float* wO = (const float*)d_in[6];
    const float* iK = (const float*)d_in[7];
    const float* iV = (const float*)d_in[8];
    float* out = (float*)d_out;

    cudaFuncSetAttribute(gemm_kvq, cudaFuncAttributeMaxDynamicSharedMemorySize, GSMB);
    cudaFuncSetAttribute(gemm_out, cudaFuncAttributeMaxDynamicSharedMemorySize, GSMB);

    // One-shot operand preparation (splits + transpose)
    split_w<<<dim3(512, 3), 256>>>(wK, wV, wQ);
    transpose_wo<<<dim3(32, 16), dim3(32, 8)>>>(wO);
    g_kernel<<<NT / 8, 256>>>(X, wG, bG);     // also emits d_Xh / d_Xl

    // K/V/Q projections on pre-split bf16 planes, fused on grid.z
    gemm_kvq<<<dim3(4, 32, 3), 256, GSMB>>>();

    gated_kernel<<<Nn * Ee * Tt, 128>>>();
    scan_kernel<<<Nn * Ee * Ll, 128>>>(iK, iV);

    static const size_t attn_smem = (512 + 2 * 128 * 65 + 8 * 128) * sizeof(float);
    cudaFuncSetAttribute(attn_kernel, cudaFuncAttributeMaxDynamicSharedMemorySize,
                         (int)attn_smem);
    attn_kernel<<<NT, 256, attn_smem>>>();

    // Output: out = Y * wO = Y * (wOT)^T
    gemm_out<<<dim3(8, 32), 256, GSMB>>>(out);
}